// round 1
// baseline (speedup 1.0000x reference)
#include <cuda_runtime.h>

// ---------------------------------------------------------------------------
// EGNN edge/node block, fp32 baseline.
// Shapes (fixed by dataset): N=50000 nodes, E=800000 edges, D=64, H=64, EF=16.
//
// Inputs (metadata order):
//  0 node_feat [N,64] f32      5 W_e1 [145,64]   9  W_n1 [128,64]
//  1 coord     [N,3]  f32      6 b_e1 [64]       10 b_n1 [64]
//  2 edge_feat [E,16] f32      7 W_e2 [64,64]    11 W_n2 [64,64]
//  3 src       [E]    i32      8 b_e2 [64]       12 b_n2 [64]
//  4 dst       [E]    i32
// Output: h [N,64] f32
// ---------------------------------------------------------------------------

#define NN      50000
#define DD      64
#define HH      64
#define EFF     16
#define KF      145      // 2*D + 1 + EF
#define KFP     148      // padded f row (148 % 32 == 20 -> conflict-free)
#define WROW    80       // padded weight row: 4 chunks of 20 floats
#define TILE    128      // rows per tile
#define THREADS 512

// scatter-sum scratch (static device memory: allowed; no allocation)
__device__ float g_hneigh[NN * HH];

__device__ __forceinline__ float silu(float x) {
    return x / (1.0f + __expf(-x));
}

__device__ __forceinline__ void red_add_v4(float* addr, float a, float b,
                                           float c, float d) {
    asm volatile("red.global.add.v4.f32 [%0], {%1,%2,%3,%4};"
                 :: "l"(addr), "f"(a), "f"(b), "f"(c), "f"(d) : "memory");
}

// ---------------------------------------------------------------------------
__global__ void zero_hneigh_kernel(int n) {
    int i = blockIdx.x * blockDim.x + threadIdx.x;
    if (i < n) g_hneigh[i] = 0.0f;
}

// ---------------------------------------------------------------------------
// Edge kernel: per edge, f = [h_src, h_dst, radial, edge_feat] (145),
// msg = silu(silu(f@W1+b1)@W2+b2), RED-add msg into g_hneigh[dst].
// Persistent blocks; weights cached in smem once.
// ---------------------------------------------------------------------------
__global__ void __launch_bounds__(THREADS, 1)
edge_kernel(const float* __restrict__ node_feat,
            const float* __restrict__ coord,
            const float* __restrict__ edge_feat,
            const int*   __restrict__ src,
            const int*   __restrict__ dst,
            const float* __restrict__ We1,
            const float* __restrict__ be1,
            const float* __restrict__ We2,
            const float* __restrict__ be2,
            int E)
{
    extern __shared__ float sm[];
    float* W1s = sm;                       // 145*80
    float* W2s = W1s + KF * WROW;          // 64*80
    float* b1s = W2s + HH * WROW;          // 64
    float* b2s = b1s + HH;                 // 64
    float* fs  = b2s + HH;                 // 128*148
    float* ms  = fs  + TILE * KFP;         // 128*68
    int*   ds  = (int*)(ms + TILE * 68);   // 128

    const int tid = threadIdx.x;

    // cache weights with chunk-skewed layout: [r][ (c/16)*20 + c%16 ]
    for (int i = tid; i < KF * HH; i += THREADS) {
        int r = i / HH, c = i % HH;
        W1s[r * WROW + (c >> 4) * 20 + (c & 15)] = We1[i];
    }
    for (int i = tid; i < HH * HH; i += THREADS) {
        int r = i / HH, c = i % HH;
        W2s[r * WROW + (c >> 4) * 20 + (c & 15)] = We2[i];
    }
    if (tid < HH) { b1s[tid] = be1[tid]; b2s[tid] = be2[tid]; }

    const int e_loc = tid >> 2;            // 0..127
    const int g     = tid & 3;             // 0..3 (output chunk of 16)
    const int warp  = tid >> 5;            // 0..15
    const int lane  = tid & 31;

    const float4* nf4 = (const float4*)node_feat;
    const float4* ef4 = (const float4*)edge_feat;

    const int nTiles = (E + TILE - 1) / TILE;
    for (int t = blockIdx.x; t < nTiles; t += gridDim.x) {
        const int base = t * TILE;
        __syncthreads();   // fs/ds reuse fence (also covers weight load, 1st iter)

        // ---- gather: warp w fills edges base + w*8 .. +7 ----
        for (int i = 0; i < 8; i++) {
            int el = warp * 8 + i;
            int eg = base + el;
            if (eg < E) {
                int s = src[eg];
                int d = dst[eg];
                float* fe = fs + el * KFP;
                if (lane < 16) {
                    ((float4*)fe)[lane] = nf4[s * 16 + lane];          // h_src
                } else {
                    ((float4*)(fe + 64))[lane - 16] = nf4[d * 16 + (lane - 16)]; // h_dst
                }
                if (lane < 4) {                                        // edge_feat
                    float4 v = ef4[eg * 4 + lane];
                    fe[129 + lane * 4 + 0] = v.x;
                    fe[129 + lane * 4 + 1] = v.y;
                    fe[129 + lane * 4 + 2] = v.z;
                    fe[129 + lane * 4 + 3] = v.w;
                }
                if (lane == 4) {                                       // radial
                    float cx = coord[s * 3 + 0] - coord[d * 3 + 0];
                    float cy = coord[s * 3 + 1] - coord[d * 3 + 1];
                    float cz = coord[s * 3 + 2] - coord[d * 3 + 2];
                    fe[128] = cx * cx + cy * cy + cz * cz;
                }
                if (lane == 5) ds[el] = d;
            }
        }
        __syncthreads();

        // ---- layer 1: m = silu(f @ W1 + b1) ----
        float acc[16];
        #pragma unroll
        for (int j = 0; j < 16; j++) acc[j] = b1s[g * 16 + j];

        const float* fe = fs + e_loc * KFP;
        const float* w1g = W1s + g * 20;
        #pragma unroll 2
        for (int k = 0; k < KF; k++) {
            float fv = fe[k];
            const float4* wr = (const float4*)(w1g + k * WROW);
            float4 w0 = wr[0], w1 = wr[1], w2 = wr[2], w3 = wr[3];
            acc[ 0] += fv * w0.x; acc[ 1] += fv * w0.y;
            acc[ 2] += fv * w0.z; acc[ 3] += fv * w0.w;
            acc[ 4] += fv * w1.x; acc[ 5] += fv * w1.y;
            acc[ 6] += fv * w1.z; acc[ 7] += fv * w1.w;
            acc[ 8] += fv * w2.x; acc[ 9] += fv * w2.y;
            acc[10] += fv * w2.z; acc[11] += fv * w2.w;
            acc[12] += fv * w3.x; acc[13] += fv * w3.y;
            acc[14] += fv * w3.z; acc[15] += fv * w3.w;
        }
        float* me = ms + e_loc * 68;
        #pragma unroll
        for (int j = 0; j < 16; j++) me[g * 16 + j] = silu(acc[j]);
        __syncthreads();

        // ---- layer 2: msg = silu(m @ W2 + b2), scatter ----
        float acc2[16];
        #pragma unroll
        for (int j = 0; j < 16; j++) acc2[j] = b2s[g * 16 + j];

        const float* w2g = W2s + g * 20;
        #pragma unroll 2
        for (int k = 0; k < HH; k++) {
            float mv = me[k];
            const float4* wr = (const float4*)(w2g + k * WROW);
            float4 w0 = wr[0], w1 = wr[1], w2 = wr[2], w3 = wr[3];
            acc2[ 0] += mv * w0.x; acc2[ 1] += mv * w0.y;
            acc2[ 2] += mv * w0.z; acc2[ 3] += mv * w0.w;
            acc2[ 4] += mv * w1.x; acc2[ 5] += mv * w1.y;
            acc2[ 6] += mv * w1.z; acc2[ 7] += mv * w1.w;
            acc2[ 8] += mv * w2.x; acc2[ 9] += mv * w2.y;
            acc2[10] += mv * w2.z; acc2[11] += mv * w2.w;
            acc2[12] += mv * w3.x; acc2[13] += mv * w3.y;
            acc2[14] += mv * w3.z; acc2[15] += mv * w3.w;
        }
        int eg = base + e_loc;
        if (eg < E) {
            float* outp = g_hneigh + (long)ds[e_loc] * HH + g * 16;
            #pragma unroll
            for (int jj = 0; jj < 4; jj++) {
                red_add_v4(outp + jj * 4,
                           silu(acc2[jj * 4 + 0]), silu(acc2[jj * 4 + 1]),
                           silu(acc2[jj * 4 + 2]), silu(acc2[jj * 4 + 3]));
            }
        }
    }
}

// ---------------------------------------------------------------------------
// Node kernel: z = [node_feat, h_neigh] (128), h = silu(z@Wn1+b)@Wn2 + b2
// ---------------------------------------------------------------------------
__global__ void __launch_bounds__(THREADS, 1)
node_kernel(const float* __restrict__ node_feat,
            const float* __restrict__ Wn1,
            const float* __restrict__ bn1,
            const float* __restrict__ Wn2,
            const float* __restrict__ bn2,
            float* __restrict__ out,
            int N)
{
    extern __shared__ float sm[];
    const int KZ  = 2 * DD;                // 128
    const int ZP  = 132;                   // padded z row
    float* W1s = sm;                       // 128*80
    float* W2s = W1s + KZ * WROW;          // 64*80
    float* b1s = W2s + HH * WROW;
    float* b2s = b1s + HH;
    float* zs  = b2s + DD;                 // 128*132
    float* hs  = zs  + TILE * ZP;          // 128*68

    const int tid = threadIdx.x;

    for (int i = tid; i < KZ * HH; i += THREADS) {
        int r = i / HH, c = i % HH;
        W1s[r * WROW + (c >> 4) * 20 + (c & 15)] = Wn1[i];
    }
    for (int i = tid; i < HH * DD; i += THREADS) {
        int r = i / DD, c = i % DD;
        W2s[r * WROW + (c >> 4) * 20 + (c & 15)] = Wn2[i];
    }
    if (tid < HH) b1s[tid] = bn1[tid];
    if (tid < DD) b2s[tid] = bn2[tid];

    const int n_loc = tid >> 2;
    const int g     = tid & 3;

    const float4* nf4 = (const float4*)node_feat;
    const float4* hn4 = (const float4*)g_hneigh;

    const int nTiles = (N + TILE - 1) / TILE;
    for (int t = blockIdx.x; t < nTiles; t += gridDim.x) {
        const int base = t * TILE;
        __syncthreads();

        // gather z = [node_feat | h_neigh] : 32 float4 per node
        for (int idx = tid; idx < TILE * 32; idx += THREADS) {
            int nl = idx >> 5, c = idx & 31;
            int n = base + nl;
            if (n < N) {
                float4 v = (c < 16) ? nf4[n * 16 + c] : hn4[n * 16 + (c - 16)];
                ((float4*)(zs + nl * ZP))[c] = v;
            }
        }
        __syncthreads();

        float acc[16];
        #pragma unroll
        for (int j = 0; j < 16; j++) acc[j] = b1s[g * 16 + j];

        const float* ze = zs + n_loc * ZP;
        const float* w1g = W1s + g * 20;
        #pragma unroll 2
        for (int k = 0; k < KZ; k++) {
            float zv = ze[k];
            const float4* wr = (const float4*)(w1g + k * WROW);
            float4 w0 = wr[0], w1 = wr[1], w2 = wr[2], w3 = wr[3];
            acc[ 0] += zv * w0.x; acc[ 1] += zv * w0.y;
            acc[ 2] += zv * w0.z; acc[ 3] += zv * w0.w;
            acc[ 4] += zv * w1.x; acc[ 5] += zv * w1.y;
            acc[ 6] += zv * w1.z; acc[ 7] += zv * w1.w;
            acc[ 8] += zv * w2.x; acc[ 9] += zv * w2.y;
            acc[10] += zv * w2.z; acc[11] += zv * w2.w;
            acc[12] += zv * w3.x; acc[13] += zv * w3.y;
            acc[14] += zv * w3.z; acc[15] += zv * w3.w;
        }
        float* he = hs + n_loc * 68;
        #pragma unroll
        for (int j = 0; j < 16; j++) he[g * 16 + j] = silu(acc[j]);
        __syncthreads();

        float acc2[16];
        #pragma unroll
        for (int j = 0; j < 16; j++) acc2[j] = b2s[g * 16 + j];

        const float* w2g = W2s + g * 20;
        #pragma unroll 2
        for (int k = 0; k < HH; k++) {
            float hv = he[k];
            const float4* wr = (const float4*)(w2g + k * WROW);
            float4 w0 = wr[0], w1 = wr[1], w2 = wr[2], w3 = wr[3];
            acc2[ 0] += hv * w0.x; acc2[ 1] += hv * w0.y;
            acc2[ 2] += hv * w0.z; acc2[ 3] += hv * w0.w;
            acc2[ 4] += hv * w1.x; acc2[ 5] += hv * w1.y;
            acc2[ 6] += hv * w1.z; acc2[ 7] += hv * w1.w;
            acc2[ 8] += hv * w2.x; acc2[ 9] += hv * w2.y;
            acc2[10] += hv * w2.z; acc2[11] += hv * w2.w;
            acc2[12] += hv * w3.x; acc2[13] += hv * w3.y;
            acc2[14] += hv * w3.z; acc2[15] += hv * w3.w;
        }
        int n = base + n_loc;
        if (n < N) {
            float4* op = (float4*)(out + (long)n * DD + g * 16);
            #pragma unroll
            for (int jj = 0; jj < 4; jj++) {
                op[jj] = make_float4(acc2[jj * 4 + 0], acc2[jj * 4 + 1],
                                     acc2[jj * 4 + 2], acc2[jj * 4 + 3]);
            }
        }
    }
}

// ---------------------------------------------------------------------------
extern "C" void kernel_launch(void* const* d_in, const int* in_sizes, int n_in,
                              void* d_out, int out_size)
{
    const float* node_feat = (const float*)d_in[0];
    const float* coord     = (const float*)d_in[1];
    const float* edge_feat = (const float*)d_in[2];
    const int*   src       = (const int*)d_in[3];
    const int*   dst       = (const int*)d_in[4];
    const float* We1       = (const float*)d_in[5];
    const float* be1       = (const float*)d_in[6];
    const float* We2       = (const float*)d_in[7];
    const float* be2       = (const float*)d_in[8];
    const float* Wn1       = (const float*)d_in[9];
    const float* bn1       = (const float*)d_in[10];
    const float* Wn2       = (const float*)d_in[11];
    const float* bn2       = (const float*)d_in[12];
    float* out = (float*)d_out;

    const int N = in_sizes[0] / DD;
    const int E = in_sizes[3];

    const size_t smem_edge =
        (size_t)(KF * WROW + HH * WROW + 2 * HH + TILE * KFP + TILE * 68 + TILE)
        * sizeof(float);
    const size_t smem_node =
        (size_t)(2 * DD * WROW + HH * WROW + HH + DD + TILE * 132 + TILE * 68)
        * sizeof(float);

    cudaFuncSetAttribute(edge_kernel,
                         cudaFuncAttributeMaxDynamicSharedMemorySize,
                         (int)smem_edge);
    cudaFuncSetAttribute(node_kernel,
                         cudaFuncAttributeMaxDynamicSharedMemorySize,
                         (int)smem_node);

    int numSMs = 148;
    cudaDeviceGetAttribute(&numSMs, cudaDevAttrMultiProcessorCount, 0);

    // 1) zero the scatter buffer
    int nh = N * HH;
    zero_hneigh_kernel<<<(nh + 511) / 512, 512>>>(nh);

    // 2) edge MLP + scatter
    int eTiles = (E + TILE - 1) / TILE;
    int eGrid = eTiles < numSMs ? eTiles : numSMs;
    edge_kernel<<<eGrid, THREADS, smem_edge>>>(
        node_feat, coord, edge_feat, src, dst, We1, be1, We2, be2, E);

    // 3) node MLP
    int nTiles = (N + TILE - 1) / TILE;
    int nGrid = nTiles < numSMs ? nTiles : numSMs;
    node_kernel<<<nGrid, THREADS, smem_node>>>(
        node_feat, Wn1, bn1, Wn2, bn2, out, N);
}

// round 2
// speedup vs baseline: 3.1048x; 3.1048x over previous
#include <cuda_runtime.h>

// ---------------------------------------------------------------------------
// EGNN edge/node block. Edge MLP on tf32 tensor cores (mma.sync m16n8k8),
// node MLP fp32 scalar. N=50000, E=800000, D=64, H=64, EF=16.
// ---------------------------------------------------------------------------

#define NN      50000
#define DD      64
#define HH      64
#define E_TILE  256
#define THREADS 512
#define FSTR    156   // f row stride (floats); 156%32=28 -> conflict-free
#define MSTR    76    // m row stride; 76%32=12 -> conflict-free
#define WSTR    72    // weight row stride; 72%32=8 -> conflict-free
#define K1P     152   // padded K of layer 1 (19 k-steps of 8)

__device__ float g_hneigh[NN * HH];

__device__ __forceinline__ float silu(float x) {
    return x / (1.0f + __expf(-x));
}

__device__ __forceinline__ unsigned f2tf(float x) {
    unsigned r;
    asm("cvt.rna.tf32.f32 %0, %1;" : "=r"(r) : "f"(x));
    return r;
}

__device__ __forceinline__ void mma_tf32(float d[4], const unsigned a[4],
                                         const unsigned b[2]) {
    asm volatile(
        "mma.sync.aligned.m16n8k8.row.col.f32.tf32.tf32.f32 "
        "{%0,%1,%2,%3}, {%4,%5,%6,%7}, {%8,%9}, {%0,%1,%2,%3};"
        : "+f"(d[0]), "+f"(d[1]), "+f"(d[2]), "+f"(d[3])
        : "r"(a[0]), "r"(a[1]), "r"(a[2]), "r"(a[3]), "r"(b[0]), "r"(b[1]));
}

__device__ __forceinline__ void cp16(unsigned saddr, const void* g) {
    asm volatile("cp.async.ca.shared.global [%0], [%1], 16;"
                 :: "r"(saddr), "l"(g));
}

__device__ __forceinline__ void red_v2(float* p, float a, float b) {
    asm volatile("red.global.add.v2.f32 [%0], {%1,%2};"
                 :: "l"(p), "f"(a), "f"(b) : "memory");
}

// ---------------------------------------------------------------------------
__global__ void zero_hneigh_kernel(int n) {
    int i = blockIdx.x * blockDim.x + threadIdx.x;
    if (i < n) g_hneigh[i] = 0.0f;
}

// ---------------------------------------------------------------------------
// Edge kernel: f = [h_src(0:64) | h_dst(64:128) | edge_feat(128:144) |
// radial(144)], msg = silu(silu(f@W1+b1)@W2+b2), RED into g_hneigh[dst].
// W1 rows permuted in smem to match the f column order.
// ---------------------------------------------------------------------------
__global__ void __launch_bounds__(THREADS, 1)
edge_kernel(const float* __restrict__ node_feat,
            const float* __restrict__ coord,
            const float* __restrict__ edge_feat,
            const int*   __restrict__ src,
            const int*   __restrict__ dst,
            const float* __restrict__ We1,
            const float* __restrict__ be1,
            const float* __restrict__ We2,
            const float* __restrict__ be2,
            int E)
{
    extern __shared__ float sm[];
    float* W1s = sm;                          // 152*72
    float* W2s = W1s + K1P * WSTR;            // 64*72
    float* b1s = W2s + HH * WSTR;             // 64
    float* b2s = b1s + HH;                    // 64
    int*   ds  = (int*)(b2s + HH);            // 256
    float* fs  = b2s + HH + E_TILE;           // 256*156 (byte off 63744, 16B ok)
    float* ms  = fs;                          // aliased (19456 <= 39936 floats)

    const int tid = threadIdx.x;

    // --- weights: tf32-rounded, layer-1 rows permuted ---
    for (int i = tid; i < K1P * HH; i += THREADS) {
        int r = i / HH, c = i % HH;
        float v = 0.0f;
        int sr = -1;
        if (r < 128)       sr = r;                 // h_src | h_dst
        else if (r < 144)  sr = 129 + (r - 128);   // edge_feat rows
        else if (r == 144) sr = 128;               // radial row
        if (sr >= 0) v = We1[sr * HH + c];
        W1s[r * WSTR + c] = __uint_as_float(f2tf(v));
    }
    for (int i = tid; i < HH * HH; i += THREADS) {
        int r = i / HH, c = i % HH;
        W2s[r * WSTR + c] = __uint_as_float(f2tf(We2[i]));
    }
    if (tid < HH) { b1s[tid] = be1[tid]; b2s[tid] = be2[tid]; }

    const int warp = tid >> 5;
    const int lane = tid & 31;
    const int gid  = lane >> 2;        // 0..7
    const int tig  = lane & 3;         // 0..3
    const int mrow  = (warp & 7) * 32; // warp's 32 output rows
    const int nbase = (warp >> 3) * 32;

    const int nTiles = (E + E_TILE - 1) / E_TILE;
    for (int t = blockIdx.x; t < nTiles; t += gridDim.x) {
        const int base = t * E_TILE;
        __syncthreads();   // fs/ms/ds reuse fence

        // ---- gather: warp handles 16 edges ----
        for (int i = 0; i < 16; i++) {
            int el  = warp * 16 + i;
            int eg  = base + el;
            int egc = eg < E ? eg : E - 1;
            int s = src[egc];
            int d = dst[egc];
            float* fe = fs + el * FSTR;
            unsigned feb = (unsigned)__cvta_generic_to_shared(fe);
            if (lane < 16)
                cp16(feb + lane * 16, node_feat + s * DD + lane * 4);
            else
                cp16(feb + 256 + (lane - 16) * 16,
                     node_feat + d * DD + (lane - 16) * 4);
            if (lane < 4)
                cp16(feb + 512 + lane * 16,
                     edge_feat + (long)egc * 16 + lane * 4);
            else if (lane == 4) {
                float cx = coord[s * 3 + 0] - coord[d * 3 + 0];
                float cy = coord[s * 3 + 1] - coord[d * 3 + 1];
                float cz = coord[s * 3 + 2] - coord[d * 3 + 2];
                fe[144] = cx * cx + cy * cy + cz * cz;
            } else if (lane == 5) {
                ds[el] = d;
            } else if (lane >= 6 && lane < 13) {
                fe[145 + (lane - 6)] = 0.0f;   // zero K pad
            }
        }
        asm volatile("cp.async.commit_group;");
        asm volatile("cp.async.wait_group 0;");
        __syncthreads();

        // ---- GEMM1: [256,152] @ [152,64] ----
        float d1[2][4][4];
        #pragma unroll
        for (int mi = 0; mi < 2; mi++)
            #pragma unroll
            for (int nj = 0; nj < 4; nj++)
                #pragma unroll
                for (int q = 0; q < 4; q++) d1[mi][nj][q] = 0.0f;

        const unsigned* w1u = (const unsigned*)W1s;
        for (int ks = 0; ks < 19; ks++) {
            const int kk = ks * 8;
            unsigned a[2][4];
            #pragma unroll
            for (int mi = 0; mi < 2; mi++) {
                int r0 = mrow + mi * 16 + gid;
                const float* fp  = fs + r0 * FSTR + kk + tig;
                const float* fp8 = fp + 8 * FSTR;
                a[mi][0] = f2tf(fp[0]);
                a[mi][1] = f2tf(fp8[0]);
                a[mi][2] = f2tf(fp[4]);
                a[mi][3] = f2tf(fp8[4]);
            }
            #pragma unroll
            for (int nj = 0; nj < 4; nj++) {
                int n = nbase + nj * 8 + gid;
                unsigned b[2];
                b[0] = w1u[(kk + tig) * WSTR + n];
                b[1] = w1u[(kk + tig + 4) * WSTR + n];
                mma_tf32(d1[0][nj], a[0], b);
                mma_tf32(d1[1][nj], a[1], b);
            }
        }
        __syncthreads();   // all fs reads done before ms overwrite (alias)

        // ---- epilogue1: bias + silu, tf32-rounded into ms ----
        #pragma unroll
        for (int mi = 0; mi < 2; mi++) {
            int r0 = mrow + mi * 16 + gid;
            #pragma unroll
            for (int nj = 0; nj < 4; nj++) {
                int c0 = nbase + nj * 8 + tig * 2;
                float bb0 = b1s[c0], bb1 = b1s[c0 + 1];
                ms[r0 * MSTR + c0]
                    = __uint_as_float(f2tf(silu(d1[mi][nj][0] + bb0)));
                ms[r0 * MSTR + c0 + 1]
                    = __uint_as_float(f2tf(silu(d1[mi][nj][1] + bb1)));
                ms[(r0 + 8) * MSTR + c0]
                    = __uint_as_float(f2tf(silu(d1[mi][nj][2] + bb0)));
                ms[(r0 + 8) * MSTR + c0 + 1]
                    = __uint_as_float(f2tf(silu(d1[mi][nj][3] + bb1)));
            }
        }
        __syncthreads();

        // ---- GEMM2: [256,64] @ [64,64] ----
        float d2[2][4][4];
        #pragma unroll
        for (int mi = 0; mi < 2; mi++)
            #pragma unroll
            for (int nj = 0; nj < 4; nj++)
                #pragma unroll
                for (int q = 0; q < 4; q++) d2[mi][nj][q] = 0.0f;

        const unsigned* msu = (const unsigned*)ms;
        const unsigned* w2u = (const unsigned*)W2s;
        for (int ks = 0; ks < 8; ks++) {
            const int kk = ks * 8;
            unsigned a[2][4];
            #pragma unroll
            for (int mi = 0; mi < 2; mi++) {
                int r0 = mrow + mi * 16 + gid;
                const unsigned* mp  = msu + r0 * MSTR + kk + tig;
                const unsigned* mp8 = mp + 8 * MSTR;
                a[mi][0] = mp[0];
                a[mi][1] = mp8[0];
                a[mi][2] = mp[4];
                a[mi][3] = mp8[4];
            }
            #pragma unroll
            for (int nj = 0; nj < 4; nj++) {
                int n = nbase + nj * 8 + gid;
                unsigned b[2];
                b[0] = w2u[(kk + tig) * WSTR + n];
                b[1] = w2u[(kk + tig + 4) * WSTR + n];
                mma_tf32(d2[0][nj], a[0], b);
                mma_tf32(d2[1][nj], a[1], b);
            }
        }

        // ---- epilogue2: bias + silu + scatter (reads ds, safe until next
        //      top-of-loop sync) ----
        #pragma unroll
        for (int mi = 0; mi < 2; mi++) {
            int r0 = mrow + mi * 16 + gid;
            #pragma unroll
            for (int nj = 0; nj < 4; nj++) {
                int c0 = nbase + nj * 8 + tig * 2;
                float bb0 = b2s[c0], bb1 = b2s[c0 + 1];
                if (base + r0 < E) {
                    red_v2(g_hneigh + (long)ds[r0] * HH + c0,
                           silu(d2[mi][nj][0] + bb0),
                           silu(d2[mi][nj][1] + bb1));
                }
                if (base + r0 + 8 < E) {
                    red_v2(g_hneigh + (long)ds[r0 + 8] * HH + c0,
                           silu(d2[mi][nj][2] + bb0),
                           silu(d2[mi][nj][3] + bb1));
                }
            }
        }
    }
}

// ---------------------------------------------------------------------------
// Node kernel (fp32 scalar, unchanged from R1): z = [node_feat, h_neigh],
// h = silu(z@Wn1+b1)@Wn2 + b2
// ---------------------------------------------------------------------------
#define WROW 80
#define TILE 128

__global__ void __launch_bounds__(THREADS, 1)
node_kernel(const float* __restrict__ node_feat,
            const float* __restrict__ Wn1,
            const float* __restrict__ bn1,
            const float* __restrict__ Wn2,
            const float* __restrict__ bn2,
            float* __restrict__ out,
            int N)
{
    extern __shared__ float sm[];
    const int KZ  = 2 * DD;                // 128
    const int ZP  = 132;
    float* W1s = sm;                       // 128*80
    float* W2s = W1s + KZ * WROW;          // 64*80
    float* b1s = W2s + HH * WROW;
    float* b2s = b1s + HH;
    float* zs  = b2s + DD;                 // 128*132
    float* hs  = zs  + TILE * ZP;          // 128*68

    const int tid = threadIdx.x;

    for (int i = tid; i < KZ * HH; i += THREADS) {
        int r = i / HH, c = i % HH;
        W1s[r * WROW + (c >> 4) * 20 + (c & 15)] = Wn1[i];
    }
    for (int i = tid; i < HH * DD; i += THREADS) {
        int r = i / DD, c = i % DD;
        W2s[r * WROW + (c >> 4) * 20 + (c & 15)] = Wn2[i];
    }
    if (tid < HH) b1s[tid] = bn1[tid];
    if (tid < DD) b2s[tid] = bn2[tid];

    const int n_loc = tid >> 2;
    const int g     = tid & 3;

    const float4* nf4 = (const float4*)node_feat;
    const float4* hn4 = (const float4*)g_hneigh;

    const int nTiles = (N + TILE - 1) / TILE;
    for (int t = blockIdx.x; t < nTiles; t += gridDim.x) {
        const int base = t * TILE;
        __syncthreads();

        for (int idx = tid; idx < TILE * 32; idx += THREADS) {
            int nl = idx >> 5, c = idx & 31;
            int n = base + nl;
            if (n < N) {
                float4 v = (c < 16) ? nf4[n * 16 + c] : hn4[n * 16 + (c - 16)];
                ((float4*)(zs + nl * ZP))[c] = v;
            }
        }
        __syncthreads();

        float acc[16];
        #pragma unroll
        for (int j = 0; j < 16; j++) acc[j] = b1s[g * 16 + j];

        const float* ze = zs + n_loc * ZP;
        const float* w1g = W1s + g * 20;
        #pragma unroll 2
        for (int k = 0; k < KZ; k++) {
            float zv = ze[k];
            const float4* wr = (const float4*)(w1g + k * WROW);
            float4 w0 = wr[0], w1 = wr[1], w2 = wr[2], w3 = wr[3];
            acc[ 0] += zv * w0.x; acc[ 1] += zv * w0.y;
            acc[ 2] += zv * w0.z; acc[ 3] += zv * w0.w;
            acc[ 4] += zv * w1.x; acc[ 5] += zv * w1.y;
            acc[ 6] += zv * w1.z; acc[ 7] += zv * w1.w;
            acc[ 8] += zv * w2.x; acc[ 9] += zv * w2.y;
            acc[10] += zv * w2.z; acc[11] += zv * w2.w;
            acc[12] += zv * w3.x; acc[13] += zv * w3.y;
            acc[14] += zv * w3.z; acc[15] += zv * w3.w;
        }
        float* he = hs + n_loc * 68;
        #pragma unroll
        for (int j = 0; j < 16; j++) he[g * 16 + j] = silu(acc[j]);
        __syncthreads();

        float acc2[16];
        #pragma unroll
        for (int j = 0; j < 16; j++) acc2[j] = b2s[g * 16 + j];

        const float* w2g = W2s + g * 20;
        #pragma unroll 2
        for (int k = 0; k < HH; k++) {
            float hv = he[k];
            const float4* wr = (const float4*)(w2g + k * WROW);
            float4 w0 = wr[0], w1 = wr[1], w2 = wr[2], w3 = wr[3];
            acc2[ 0] += hv * w0.x; acc2[ 1] += hv * w0.y;
            acc2[ 2] += hv * w0.z; acc2[ 3] += hv * w0.w;
            acc2[ 4] += hv * w1.x; acc2[ 5] += hv * w1.y;
            acc2[ 6] += hv * w1.z; acc2[ 7] += hv * w1.w;
            acc2[ 8] += hv * w2.x; acc2[ 9] += hv * w2.y;
            acc2[10] += hv * w2.z; acc2[11] += hv * w2.w;
            acc2[12] += hv * w3.x; acc2[13] += hv * w3.y;
            acc2[14] += hv * w3.z; acc2[15] += hv * w3.w;
        }
        int n = base + n_loc;
        if (n < N) {
            float4* op = (float4*)(out + (long)n * DD + g * 16);
            #pragma unroll
            for (int jj = 0; jj < 4; jj++) {
                op[jj] = make_float4(acc2[jj * 4 + 0], acc2[jj * 4 + 1],
                                     acc2[jj * 4 + 2], acc2[jj * 4 + 3]);
            }
        }
    }
}

// ---------------------------------------------------------------------------
extern "C" void kernel_launch(void* const* d_in, const int* in_sizes, int n_in,
                              void* d_out, int out_size)
{
    const float* node_feat = (const float*)d_in[0];
    const float* coord     = (const float*)d_in[1];
    const float* edge_feat = (const float*)d_in[2];
    const int*   src       = (const int*)d_in[3];
    const int*   dst       = (const int*)d_in[4];
    const float* We1       = (const float*)d_in[5];
    const float* be1       = (const float*)d_in[6];
    const float* We2       = (const float*)d_in[7];
    const float* be2       = (const float*)d_in[8];
    const float* Wn1       = (const float*)d_in[9];
    const float* bn1       = (const float*)d_in[10];
    const float* Wn2       = (const float*)d_in[11];
    const float* bn2       = (const float*)d_in[12];
    float* out = (float*)d_out;

    const int N = in_sizes[0] / DD;
    const int E = in_sizes[3];

    const size_t smem_edge =
        (size_t)(K1P * WSTR + HH * WSTR + 2 * HH + E_TILE + E_TILE * FSTR)
        * sizeof(float);   // 223488 B
    const size_t smem_node =
        (size_t)(2 * DD * WROW + HH * WROW + HH + DD + TILE * 132 + TILE * 68)
        * sizeof(float);

    cudaFuncSetAttribute(edge_kernel,
                         cudaFuncAttributeMaxDynamicSharedMemorySize,
                         (int)smem_edge);
    cudaFuncSetAttribute(node_kernel,
                         cudaFuncAttributeMaxDynamicSharedMemorySize,
                         (int)smem_node);

    int numSMs = 148;
    cudaDeviceGetAttribute(&numSMs, cudaDevAttrMultiProcessorCount, 0);

    int nh = N * HH;
    zero_hneigh_kernel<<<(nh + 511) / 512, 512>>>(nh);

    int eTiles = (E + E_TILE - 1) / E_TILE;
    int eGrid = eTiles < numSMs ? eTiles : numSMs;
    edge_kernel<<<eGrid, THREADS, smem_edge>>>(
        node_feat, coord, edge_feat, src, dst, We1, be1, We2, be2, E);

    int nTiles = (N + TILE - 1) / TILE;
    int nGrid = nTiles < numSMs ? nTiles : numSMs;
    node_kernel<<<nGrid, THREADS, smem_node>>>(
        node_feat, Wn1, bn1, Wn2, bn2, out, N);
}

// round 3
// speedup vs baseline: 3.3793x; 1.0884x over previous
#include <cuda_runtime.h>

// ---------------------------------------------------------------------------
// EGNN edge/node block. tf32 mma.sync everywhere; edge kernel warp-specialized
// (8 producer warps: gather + red.v4 scatter; 8 consumer warps: GEMMs),
// double-buffered. N=50000, E=800000, D=64, H=64, EF=16.
// ---------------------------------------------------------------------------

#define NN      50000
#define DD      64
#define HH      64
#define E_TILE  128
#define THREADS 512
#define FSTR    156    // f row stride; 156%32=28 conflict-free; 624B row, 16B ok
#define MSTR    76     // m/msg row stride; 76%32=12 conflict-free
#define WSTR    72     // weight row stride; 72%32=8 conflict-free
#define K1P     152    // padded K of edge layer 1 (19 k-steps of 8)
#define BUFSZ   19968  // floats per buffer (128*156)
#define MSGOFF  9984   // msg region offset inside buffer (floats)

__device__ float g_hneigh[NN * HH];

__device__ __forceinline__ float silu(float x) {
    return x / (1.0f + __expf(-x));
}
__device__ __forceinline__ unsigned f2tf(float x) {
    unsigned r;
    asm("cvt.rna.tf32.f32 %0, %1;" : "=r"(r) : "f"(x));
    return r;
}
__device__ __forceinline__ void mma_tf32(float d[4], const unsigned a[4],
                                         const unsigned b[2]) {
    asm volatile(
        "mma.sync.aligned.m16n8k8.row.col.f32.tf32.tf32.f32 "
        "{%0,%1,%2,%3}, {%4,%5,%6,%7}, {%8,%9}, {%0,%1,%2,%3};"
        : "+f"(d[0]), "+f"(d[1]), "+f"(d[2]), "+f"(d[3])
        : "r"(a[0]), "r"(a[1]), "r"(a[2]), "r"(a[3]), "r"(b[0]), "r"(b[1]));
}
__device__ __forceinline__ void cp16(unsigned saddr, const void* g) {
    asm volatile("cp.async.ca.shared.global [%0], [%1], 16;"
                 :: "r"(saddr), "l"(g));
}
__device__ __forceinline__ void red_v4(float* p, float4 v) {
    asm volatile("red.global.add.v4.f32 [%0], {%1,%2,%3,%4};"
                 :: "l"(p), "f"(v.x), "f"(v.y), "f"(v.z), "f"(v.w) : "memory");
}
__device__ __forceinline__ void bar_sync(int id, int cnt) {
    asm volatile("bar.sync %0, %1;" :: "r"(id), "r"(cnt) : "memory");
}
__device__ __forceinline__ void bar_arrive(int id, int cnt) {
    asm volatile("bar.arrive %0, %1;" :: "r"(id), "r"(cnt) : "memory");
}

// ---------------------------------------------------------------------------
__global__ void zero_hneigh_kernel(int n) {
    int i = blockIdx.x * blockDim.x + threadIdx.x;
    if (i < n) g_hneigh[i] = 0.0f;
}

// ---------------------------------------------------------------------------
// Edge kernel. f = [h_src(0:64)|h_dst(64:128)|edge_feat(128:144)|radial(144)].
// Named barriers: 1+b = FULL[b] (prod arrive, cons sync),
//                 3+b = MSGRDY[b] (cons arrive, prod sync), 5 = cons, 6 = prod.
// ---------------------------------------------------------------------------
__global__ void __launch_bounds__(THREADS, 1)
edge_kernel(const float* __restrict__ node_feat,
            const float* __restrict__ coord,
            const float* __restrict__ edge_feat,
            const int*   __restrict__ src,
            const int*   __restrict__ dst,
            const float* __restrict__ We1,
            const float* __restrict__ be1,
            const float* __restrict__ We2,
            const float* __restrict__ be2,
            int E)
{
    extern __shared__ float sm[];
    float* buf0 = sm;                       // 19968
    float* buf1 = sm + BUFSZ;               // 19968
    float* W1s  = sm + 2 * BUFSZ;           // 152*72
    float* W2s  = W1s + K1P * WSTR;         // 64*72
    float* b1s  = W2s + HH * WSTR;          // 64
    float* b2s  = b1s + HH;                 // 64
    int*   ds0  = (int*)(b2s + HH);         // 128
    int*   ds1  = ds0 + E_TILE;             // 128

    const int tid = threadIdx.x;

    // weights (tf32, layer-1 rows permuted to f column order)
    for (int i = tid; i < K1P * HH; i += THREADS) {
        int r = i / HH, c = i % HH;
        float v = 0.0f;
        int sr = -1;
        if (r < 128)       sr = r;
        else if (r < 144)  sr = 129 + (r - 128);
        else if (r == 144) sr = 128;
        if (sr >= 0) v = We1[sr * HH + c];
        W1s[r * WSTR + c] = __uint_as_float(f2tf(v));
    }
    for (int i = tid; i < HH * HH; i += THREADS) {
        int r = i / HH, c = i % HH;
        W2s[r * WSTR + c] = __uint_as_float(f2tf(We2[i]));
    }
    if (tid < HH) { b1s[tid] = be1[tid]; b2s[tid] = be2[tid]; }
    __syncthreads();

    const int warp = tid >> 5;
    const int lane = tid & 31;
    const int nTiles = (E + E_TILE - 1) / E_TILE;
    // stages this block owns: tiles t = bid + s*grid
    int nS = 0;
    for (long t = blockIdx.x; t < nTiles; t += gridDim.x) nS++;
    if (nS == 0) return;

    if (warp >= 8) {
        // ================= PRODUCERS (warps 8..15) =================
        const int w = warp - 8;
        const float4* nf4 = (const float4*)node_feat;
        const float4* ef4 = (const float4*)edge_feat;

        for (int s = 0; s < nS + 2; s++) {
            const int b = s & 1;
            float* buf = b ? buf1 : buf0;
            int*   ds  = b ? ds1 : ds0;

            if (s >= 2) {
                // wait consumer msg for tile s-2 (same buffer), scatter it
                bar_sync(3 + b, THREADS);
                const int pbase = ((s - 2) * gridDim.x + blockIdx.x) * E_TILE;
                const int rbase = w * 16;
                #pragma unroll 2
                for (int i = 0; i < 8; i++) {
                    int r = rbase + i * 2 + (lane >> 4);
                    int c = (lane & 15) * 4;
                    if (pbase + r < E) {
                        float4 v = *(const float4*)(buf + MSGOFF + r * MSTR + c);
                        red_v4(g_hneigh + (long)ds[r] * HH + c, v);
                    }
                }
            }
            if (s >= nS) continue;       // drain stages: RED only
            if (s >= 2) bar_sync(6, 256); // all REDs done before refill

            // gather tile s into buf
            const int base = (s * gridDim.x + blockIdx.x) * E_TILE;
            for (int i = 0; i < 16; i++) {
                int el  = w * 16 + i;
                int eg  = base + el;
                int egc = eg < E ? eg : E - 1;
                int ss = src[egc];
                int dd = dst[egc];
                float* fe = buf + el * FSTR;
                unsigned feb = (unsigned)__cvta_generic_to_shared(fe);
                if (lane < 16)
                    cp16(feb + lane * 16, node_feat + ss * DD + lane * 4);
                else
                    cp16(feb + 256 + (lane - 16) * 16,
                         node_feat + dd * DD + (lane - 16) * 4);
                if (lane < 4)
                    cp16(feb + 512 + lane * 16,
                         edge_feat + (long)egc * 16 + lane * 4);
                else if (lane == 4) {
                    float cx = coord[ss * 3 + 0] - coord[dd * 3 + 0];
                    float cy = coord[ss * 3 + 1] - coord[dd * 3 + 1];
                    float cz = coord[ss * 3 + 2] - coord[dd * 3 + 2];
                    fe[144] = cx * cx + cy * cy + cz * cz;
                } else if (lane == 5) {
                    ds[el] = dd;
                } else if (lane >= 6 && lane < 13) {
                    fe[145 + (lane - 6)] = 0.0f;
                }
                (void)nf4; (void)ef4;
            }
            asm volatile("cp.async.commit_group;");
            asm volatile("cp.async.wait_group 0;");
            bar_arrive(1 + b, THREADS);   // FULL[b]
        }
    } else {
        // ================= CONSUMERS (warps 0..7) =================
        const int gid  = lane >> 2;
        const int tig  = lane & 3;
        const int mrow  = (warp & 3) * 32;
        const int nbase = (warp >> 2) * 32;

        for (int s = 0; s < nS; s++) {
            const int b = s & 1;
            float* buf = b ? buf1 : buf0;
            bar_sync(1 + b, THREADS);     // wait FULL[b]

            // ---- GEMM1: [128,152]@[152,64] ----
            float d1[2][4][4];
            #pragma unroll
            for (int mi = 0; mi < 2; mi++)
                #pragma unroll
                for (int nj = 0; nj < 4; nj++)
                    #pragma unroll
                    for (int q = 0; q < 4; q++) d1[mi][nj][q] = 0.0f;

            const unsigned* w1u = (const unsigned*)W1s;
            for (int ks = 0; ks < 19; ks++) {
                const int kk = ks * 8;
                unsigned a[2][4];
                #pragma unroll
                for (int mi = 0; mi < 2; mi++) {
                    int r0 = mrow + mi * 16 + gid;
                    const float* fp  = buf + r0 * FSTR + kk + tig;
                    const float* fp8 = fp + 8 * FSTR;
                    a[mi][0] = f2tf(fp[0]);
                    a[mi][1] = f2tf(fp8[0]);
                    a[mi][2] = f2tf(fp[4]);
                    a[mi][3] = f2tf(fp8[4]);
                }
                #pragma unroll
                for (int nj = 0; nj < 4; nj++) {
                    int n = nbase + nj * 8 + gid;
                    unsigned bb[2];
                    bb[0] = w1u[(kk + tig) * WSTR + n];
                    bb[1] = w1u[(kk + tig + 4) * WSTR + n];
                    mma_tf32(d1[0][nj], a[0], bb);
                    mma_tf32(d1[1][nj], a[1], bb);
                }
            }
            bar_sync(5, 256);             // f reads done before m overwrite

            // ---- epilogue1: bias + silu -> m (tf32) at buf[0..9728) ----
            #pragma unroll
            for (int mi = 0; mi < 2; mi++) {
                int r0 = mrow + mi * 16 + gid;
                #pragma unroll
                for (int nj = 0; nj < 4; nj++) {
                    int c0 = nbase + nj * 8 + tig * 2;
                    float bb0 = b1s[c0], bb1 = b1s[c0 + 1];
                    buf[r0 * MSTR + c0]
                        = __uint_as_float(f2tf(silu(d1[mi][nj][0] + bb0)));
                    buf[r0 * MSTR + c0 + 1]
                        = __uint_as_float(f2tf(silu(d1[mi][nj][1] + bb1)));
                    buf[(r0 + 8) * MSTR + c0]
                        = __uint_as_float(f2tf(silu(d1[mi][nj][2] + bb0)));
                    buf[(r0 + 8) * MSTR + c0 + 1]
                        = __uint_as_float(f2tf(silu(d1[mi][nj][3] + bb1)));
                }
            }
            bar_sync(5, 256);

            // ---- GEMM2: [128,64]@[64,64] ----
            float d2[2][4][4];
            #pragma unroll
            for (int mi = 0; mi < 2; mi++)
                #pragma unroll
                for (int nj = 0; nj < 4; nj++)
                    #pragma unroll
                    for (int q = 0; q < 4; q++) d2[mi][nj][q] = 0.0f;

            const unsigned* msu = (const unsigned*)buf;
            const unsigned* w2u = (const unsigned*)W2s;
            for (int ks = 0; ks < 8; ks++) {
                const int kk = ks * 8;
                unsigned a[2][4];
                #pragma unroll
                for (int mi = 0; mi < 2; mi++) {
                    int r0 = mrow + mi * 16 + gid;
                    const unsigned* mp  = msu + r0 * MSTR + kk + tig;
                    const unsigned* mp8 = mp + 8 * MSTR;
                    a[mi][0] = mp[0];
                    a[mi][1] = mp8[0];
                    a[mi][2] = mp[4];
                    a[mi][3] = mp8[4];
                }
                #pragma unroll
                for (int nj = 0; nj < 4; nj++) {
                    int n = nbase + nj * 8 + gid;
                    unsigned bb[2];
                    bb[0] = w2u[(kk + tig) * WSTR + n];
                    bb[1] = w2u[(kk + tig + 4) * WSTR + n];
                    mma_tf32(d2[0][nj], a[0], bb);
                    mma_tf32(d2[1][nj], a[1], bb);
                }
            }

            // ---- epilogue2: bias + silu -> msg region (disjoint from m) ----
            #pragma unroll
            for (int mi = 0; mi < 2; mi++) {
                int r0 = mrow + mi * 16 + gid;
                #pragma unroll
                for (int nj = 0; nj < 4; nj++) {
                    int c0 = nbase + nj * 8 + tig * 2;
                    float bb0 = b2s[c0], bb1 = b2s[c0 + 1];
                    buf[MSGOFF + r0 * MSTR + c0]     = silu(d2[mi][nj][0] + bb0);
                    buf[MSGOFF + r0 * MSTR + c0 + 1] = silu(d2[mi][nj][1] + bb1);
                    buf[MSGOFF + (r0 + 8) * MSTR + c0]     = silu(d2[mi][nj][2] + bb0);
                    buf[MSGOFF + (r0 + 8) * MSTR + c0 + 1] = silu(d2[mi][nj][3] + bb1);
                }
            }
            bar_arrive(3 + b, THREADS);   // MSGRDY[b]
        }
    }
}

// ---------------------------------------------------------------------------
// Node kernel: tf32 mma. z = [node_feat | h_neigh] (K=128),
// h = silu(z@Wn1+b1)@Wn2 + b2. 256-row tiles, 16 warps (8 row x 2 col groups).
// ---------------------------------------------------------------------------
#define N_TILE 256
#define ZSTR   132

__global__ void __launch_bounds__(THREADS, 1)
node_kernel(const float* __restrict__ node_feat,
            const float* __restrict__ Wn1,
            const float* __restrict__ bn1,
            const float* __restrict__ Wn2,
            const float* __restrict__ bn2,
            float* __restrict__ out,
            int N)
{
    extern __shared__ float sm[];
    float* zs  = sm;                        // 256*132 (m aliases, stride 76)
    float* W1s = zs + N_TILE * ZSTR;        // 128*72
    float* W2s = W1s + 128 * WSTR;          // 64*72
    float* b1s = W2s + HH * WSTR;
    float* b2s = b1s + HH;

    const int tid = threadIdx.x;

    for (int i = tid; i < 128 * HH; i += THREADS) {
        int r = i / HH, c = i % HH;
        W1s[r * WSTR + c] = __uint_as_float(f2tf(Wn1[i]));
    }
    for (int i = tid; i < HH * DD; i += THREADS) {
        int r = i / DD, c = i % DD;
        W2s[r * WSTR + c] = __uint_as_float(f2tf(Wn2[i]));
    }
    if (tid < HH) { b1s[tid] = bn1[tid]; b2s[tid] = bn2[tid]; }

    const int warp = tid >> 5;
    const int lane = tid & 31;
    const int gid  = lane >> 2;
    const int tig  = lane & 3;
    const int mrow  = (warp & 7) * 32;
    const int nbase = (warp >> 3) * 32;

    const float4* nf4 = (const float4*)node_feat;
    const float4* hn4 = (const float4*)g_hneigh;

    const int nTiles = (N + N_TILE - 1) / N_TILE;
    for (int t = blockIdx.x; t < nTiles; t += gridDim.x) {
        const int base = t * N_TILE;
        __syncthreads();

        // gather z = [nf | hneigh]: 32 float4 per row
        for (int idx = tid; idx < N_TILE * 32; idx += THREADS) {
            int nl = idx >> 5, c = idx & 31;
            int n = base + nl;
            if (n >= N) n = N - 1;
            float4 v = (c < 16) ? nf4[n * 16 + c] : hn4[(long)n * 16 + (c - 16)];
            ((float4*)(zs + nl * ZSTR))[c] = v;
        }
        __syncthreads();

        // GEMM1: [256,128]@[128,64]
        float d1[2][4][4];
        #pragma unroll
        for (int mi = 0; mi < 2; mi++)
            #pragma unroll
            for (int nj = 0; nj < 4; nj++)
                #pragma unroll
                for (int q = 0; q < 4; q++) d1[mi][nj][q] = 0.0f;

        const unsigned* w1u = (const unsigned*)W1s;
        for (int ks = 0; ks < 16; ks++) {
            const int kk = ks * 8;
            unsigned a[2][4];
            #pragma unroll
            for (int mi = 0; mi < 2; mi++) {
                int r0 = mrow + mi * 16 + gid;
                const float* fp  = zs + r0 * ZSTR + kk + tig;
                const float* fp8 = fp + 8 * ZSTR;
                a[mi][0] = f2tf(fp[0]);
                a[mi][1] = f2tf(fp8[0]);
                a[mi][2] = f2tf(fp[4]);
                a[mi][3] = f2tf(fp8[4]);
            }
            #pragma unroll
            for (int nj = 0; nj < 4; nj++) {
                int n = nbase + nj * 8 + gid;
                unsigned bb[2];
                bb[0] = w1u[(kk + tig) * WSTR + n];
                bb[1] = w1u[(kk + tig + 4) * WSTR + n];
                mma_tf32(d1[0][nj], a[0], bb);
                mma_tf32(d1[1][nj], a[1], bb);
            }
        }
        __syncthreads();   // z reads done before m overwrite

        #pragma unroll
        for (int mi = 0; mi < 2; mi++) {
            int r0 = mrow + mi * 16 + gid;
            #pragma unroll
            for (int nj = 0; nj < 4; nj++) {
                int c0 = nbase + nj * 8 + tig * 2;
                float bb0 = b1s[c0], bb1 = b1s[c0 + 1];
                zs[r0 * MSTR + c0]
                    = __uint_as_float(f2tf(silu(d1[mi][nj][0] + bb0)));
                zs[r0 * MSTR + c0 + 1]
                    = __uint_as_float(f2tf(silu(d1[mi][nj][1] + bb1)));
                zs[(r0 + 8) * MSTR + c0]
                    = __uint_as_float(f2tf(silu(d1[mi][nj][2] + bb0)));
                zs[(r0 + 8) * MSTR + c0 + 1]
                    = __uint_as_float(f2tf(silu(d1[mi][nj][3] + bb1)));
            }
        }
        __syncthreads();

        // GEMM2: [256,64]@[64,64]
        float d2[2][4][4];
        #pragma unroll
        for (int mi = 0; mi < 2; mi++)
            #pragma unroll
            for (int nj = 0; nj < 4; nj++)
                #pragma unroll
                for (int q = 0; q < 4; q++) d2[mi][nj][q] = 0.0f;

        const unsigned* msu = (const unsigned*)zs;
        const unsigned* w2u = (const unsigned*)W2s;
        for (int ks = 0; ks < 8; ks++) {
            const int kk = ks * 8;
            unsigned a[2][4];
            #pragma unroll
            for (int mi = 0; mi < 2; mi++) {
                int r0 = mrow + mi * 16 + gid;
                const unsigned* mp  = msu + r0 * MSTR + kk + tig;
                const unsigned* mp8 = mp + 8 * MSTR;
                a[mi][0] = mp[0];
                a[mi][1] = mp8[0];
                a[mi][2] = mp[4];
                a[mi][3] = mp8[4];
            }
            #pragma unroll
            for (int nj = 0; nj < 4; nj++) {
                int n = nbase + nj * 8 + gid;
                unsigned bb[2];
                bb[0] = w2u[(kk + tig) * WSTR + n];
                bb[1] = w2u[(kk + tig + 4) * WSTR + n];
                mma_tf32(d2[0][nj], a[0], bb);
                mma_tf32(d2[1][nj], a[1], bb);
            }
        }

        #pragma unroll
        for (int mi = 0; mi < 2; mi++) {
            int r0 = mrow + mi * 16 + gid;
            #pragma unroll
            for (int nj = 0; nj < 4; nj++) {
                int c0 = nbase + nj * 8 + tig * 2;
                float bb0 = b2s[c0], bb1 = b2s[c0 + 1];
                int n0 = base + r0, n1 = base + r0 + 8;
                if (n0 < N)
                    *(float2*)(out + (long)n0 * DD + c0)
                        = make_float2(d2[mi][nj][0] + bb0, d2[mi][nj][1] + bb1);
                if (n1 < N)
                    *(float2*)(out + (long)n1 * DD + c0)
                        = make_float2(d2[mi][nj][2] + bb0, d2[mi][nj][3] + bb1);
            }
        }
    }
}

// ---------------------------------------------------------------------------
extern "C" void kernel_launch(void* const* d_in, const int* in_sizes, int n_in,
                              void* d_out, int out_size)
{
    const float* node_feat = (const float*)d_in[0];
    const float* coord     = (const float*)d_in[1];
    const float* edge_feat = (const float*)d_in[2];
    const int*   src       = (const int*)d_in[3];
    const int*   dst       = (const int*)d_in[4];
    const float* We1       = (const float*)d_in[5];
    const float* be1       = (const float*)d_in[6];
    const float* We2       = (const float*)d_in[7];
    const float* be2       = (const float*)d_in[8];
    const float* Wn1       = (const float*)d_in[9];
    const float* bn1       = (const float*)d_in[10];
    const float* Wn2       = (const float*)d_in[11];
    const float* bn2       = (const float*)d_in[12];
    float* out = (float*)d_out;

    const int N = in_sizes[0] / DD;
    const int E = in_sizes[3];

    const size_t smem_edge =
        (size_t)(2 * BUFSZ + K1P * WSTR + HH * WSTR + 2 * HH + 2 * E_TILE)
        * sizeof(float);   // 223488 B
    const size_t smem_node =
        (size_t)(N_TILE * ZSTR + 128 * WSTR + HH * WSTR + 2 * HH)
        * sizeof(float);   // ~190 KB

    cudaFuncSetAttribute(edge_kernel,
                         cudaFuncAttributeMaxDynamicSharedMemorySize,
                         (int)smem_edge);
    cudaFuncSetAttribute(node_kernel,
                         cudaFuncAttributeMaxDynamicSharedMemorySize,
                         (int)smem_node);

    int numSMs = 148;
    cudaDeviceGetAttribute(&numSMs, cudaDevAttrMultiProcessorCount, 0);

    int nh = N * HH;
    zero_hneigh_kernel<<<(nh + 511) / 512, 512>>>(nh);

    int eTiles = (E + E_TILE - 1) / E_TILE;
    int eGrid = eTiles < numSMs ? eTiles : numSMs;
    edge_kernel<<<eGrid, THREADS, smem_edge>>>(
        node_feat, coord, edge_feat, src, dst, We1, be1, We2, be2, E);

    int nTiles = (N + N_TILE - 1) / N_TILE;
    int nGrid = nTiles < numSMs ? nTiles : numSMs;
    node_kernel<<<nGrid, THREADS, smem_node>>>(
        node_feat, Wn1, bn1, Wn2, bn2, out, N);
}

// round 4
// speedup vs baseline: 3.8561x; 1.1411x over previous
#include <cuda_runtime.h>

// ---------------------------------------------------------------------------
// EGNN edge/node block, round 4.
// Algebraic refactor: P[n] = [h_n@W1_src | h_n@W1_dst] precomputed once
// ([N,64]@[64,128]); edge layer-1 shrinks to K=24 (edge_feat+radial) plus a
// gathered fp32 add of P rows. Edge kernel: 256 threads, 2 CTAs/SM, simple
// phase loop (gather -> GEMM1 -> GEMM2 -> scatter), tf32 mma.sync.
// N=50000, E=800000, D=64, H=64, EF=16.
// ---------------------------------------------------------------------------

#define NN      50000
#define DD      64
#define HH      64
#define E_TILE  128
#define WSTR    72     // weight row stride (72%32=8, conflict-free)
#define PSTR    68     // presum/msg row stride (68%32=4)
#define FSSTR   28     // fsmall row stride (28%32=28, conflict-free)
#define MSTR    68     // m row stride
#define K1S     24     // padded small-K of edge layer 1 (3 k-steps)

__device__ float g_hneigh[NN * HH];
__device__ float g_P[NN * 128];        // [n][0:64]=h@W1_src, [64:128]=h@W1_dst

__device__ __forceinline__ float silu(float x) {
    return x / (1.0f + __expf(-x));
}
__device__ __forceinline__ unsigned f2tf(float x) {
    unsigned r;
    asm("cvt.rna.tf32.f32 %0, %1;" : "=r"(r) : "f"(x));
    return r;
}
__device__ __forceinline__ void mma_tf32(float d[4], const unsigned a[4],
                                         const unsigned b[2]) {
    asm volatile(
        "mma.sync.aligned.m16n8k8.row.col.f32.tf32.tf32.f32 "
        "{%0,%1,%2,%3}, {%4,%5,%6,%7}, {%8,%9}, {%0,%1,%2,%3};"
        : "+f"(d[0]), "+f"(d[1]), "+f"(d[2]), "+f"(d[3])
        : "r"(a[0]), "r"(a[1]), "r"(a[2]), "r"(a[3]), "r"(b[0]), "r"(b[1]));
}
__device__ __forceinline__ void red_v4(float* p, float4 v) {
    asm volatile("red.global.add.v4.f32 [%0], {%1,%2,%3,%4};"
                 :: "l"(p), "f"(v.x), "f"(v.y), "f"(v.z), "f"(v.w) : "memory");
}

// ---------------------------------------------------------------------------
__global__ void zero_hneigh_kernel(int n) {
    int i = blockIdx.x * blockDim.x + threadIdx.x;
    if (i < n) g_hneigh[i] = 0.0f;
}

// ---------------------------------------------------------------------------
// P kernel: P = node_feat @ [W1_src | W1_dst]  ([N,64]@[64,128], tf32 mma)
// 512 threads = 16 warps, warp tile 32x32 over a 128x128 output tile.
// ---------------------------------------------------------------------------
#define ASTR  68
#define BSTR2 136

__global__ void __launch_bounds__(512, 1)
p_kernel(const float* __restrict__ node_feat,
         const float* __restrict__ We1,
         int N)
{
    extern __shared__ float sm[];
    float* As = sm;                 // 128*68
    float* Bs = As + 128 * ASTR;    // 64*136

    const int tid = threadIdx.x;
    // B: cols 0-63 from We1 rows 0-63 (src), cols 64-127 from rows 64-127 (dst)
    for (int i = tid; i < 64 * 128; i += 512) {
        int k = i >> 7, j = i & 127;
        float v = (j < 64) ? We1[k * HH + j] : We1[(64 + k) * HH + (j - 64)];
        Bs[k * BSTR2 + j] = __uint_as_float(f2tf(v));
    }
    const int base = blockIdx.x * 128;
    const float4* nf4 = (const float4*)node_feat;
    for (int idx = tid; idx < 128 * 16; idx += 512) {
        int r = idx >> 4, c = idx & 15;
        int n = base + r;
        if (n >= N) n = N - 1;
        ((float4*)(As + r * ASTR))[c] = nf4[(long)n * 16 + c];
    }
    __syncthreads();

    const int warp = tid >> 5, lane = tid & 31;
    const int gid = lane >> 2, tig = lane & 3;
    const int mrow  = (warp & 3) * 32;
    const int nbase = (warp >> 2) * 32;

    float d[2][4][4];
    #pragma unroll
    for (int mi = 0; mi < 2; mi++)
        #pragma unroll
        for (int nj = 0; nj < 4; nj++)
            #pragma unroll
            for (int q = 0; q < 4; q++) d[mi][nj][q] = 0.0f;

    const unsigned* bu = (const unsigned*)Bs;
    for (int ks = 0; ks < 8; ks++) {
        const int kk = ks * 8;
        unsigned a[2][4];
        #pragma unroll
        for (int mi = 0; mi < 2; mi++) {
            int r0 = mrow + mi * 16 + gid;
            const float* fp  = As + r0 * ASTR + kk + tig;
            const float* fp8 = fp + 8 * ASTR;
            a[mi][0] = f2tf(fp[0]);
            a[mi][1] = f2tf(fp8[0]);
            a[mi][2] = f2tf(fp[4]);
            a[mi][3] = f2tf(fp8[4]);
        }
        #pragma unroll
        for (int nj = 0; nj < 4; nj++) {
            int n = nbase + nj * 8 + gid;
            unsigned bb[2];
            bb[0] = bu[(kk + tig) * BSTR2 + n];
            bb[1] = bu[(kk + tig + 4) * BSTR2 + n];
            mma_tf32(d[0][nj], a[0], bb);
            mma_tf32(d[1][nj], a[1], bb);
        }
    }
    #pragma unroll
    for (int mi = 0; mi < 2; mi++) {
        int r0 = mrow + mi * 16 + gid;
        #pragma unroll
        for (int nj = 0; nj < 4; nj++) {
            int c0 = nbase + nj * 8 + tig * 2;
            int n0 = base + r0, n1 = base + r0 + 8;
            if (n0 < N)
                *(float2*)(g_P + (long)n0 * 128 + c0)
                    = make_float2(d[mi][nj][0], d[mi][nj][1]);
            if (n1 < N)
                *(float2*)(g_P + (long)n1 * 128 + c0)
                    = make_float2(d[mi][nj][2], d[mi][nj][3]);
        }
    }
}

// ---------------------------------------------------------------------------
// Edge kernel. Per tile of 128 edges:
//   gather: presum[e] = P[src][0:64] + P[dst][64:128]  (fp32),
//           fsmall[e] = [edge_feat(16), radial, 0-pad] (K=24), ds[e]=dst
//   GEMM1 (3 ksteps): g = fsmall @ W1small ; m = tf32(silu(g + presum + b1))
//   GEMM2 (8 ksteps): msg = silu(m @ W2 + b2)
//   scatter: red.v4 msg into g_hneigh[dst]
// 256 threads (8 warps: 4 row-groups x 2 col-groups), persistent, 2 CTAs/SM.
// ---------------------------------------------------------------------------
#define ETHREADS 256

__global__ void __launch_bounds__(ETHREADS, 2)
edge_kernel(const float* __restrict__ coord,
            const float* __restrict__ edge_feat,
            const int*   __restrict__ src,
            const int*   __restrict__ dst,
            const float* __restrict__ We1,
            const float* __restrict__ be1,
            const float* __restrict__ We2,
            const float* __restrict__ be2,
            int E)
{
    extern __shared__ float sm[];
    float* W1s    = sm;                    // 24*72   = 1728
    float* W2s    = W1s + K1S * WSTR;      // 64*72   = 4608
    float* b1s    = W2s + HH * WSTR;       // 64
    float* b2s    = b1s + HH;              // 64
    int*   ds     = (int*)(b2s + HH);      // 128
    float* presum = (float*)(ds + E_TILE); // 128*68 (msg aliases this)
    float* fsmall = presum + E_TILE * PSTR;// 128*28
    float* m      = fsmall + E_TILE * FSSTR; // 128*68
    float* msg    = presum;                // alias

    const int tid = threadIdx.x;

    // W1small rows: 0-15 = edge_feat rows (orig 129-144), 16 = radial (128)
    for (int i = tid; i < K1S * HH; i += ETHREADS) {
        int r = i / HH, c = i % HH;
        float v = 0.0f;
        if (r < 16)       v = We1[(129 + r) * HH + c];
        else if (r == 16) v = We1[128 * HH + c];
        W1s[r * WSTR + c] = __uint_as_float(f2tf(v));
    }
    for (int i = tid; i < HH * HH; i += ETHREADS) {
        int r = i / HH, c = i % HH;
        W2s[r * WSTR + c] = __uint_as_float(f2tf(We2[i]));
    }
    if (tid < HH) { b1s[tid] = be1[tid]; b2s[tid] = be2[tid]; }

    const int warp = tid >> 5;
    const int lane = tid & 31;
    const int gid  = lane >> 2;
    const int tig  = lane & 3;
    const int mrow  = (warp & 3) * 32;
    const int nbase = (warp >> 2) * 32;
    const int half  = lane >> 4;           // 0/1
    const int j     = lane & 15;           // 0..15

    const float4* P4  = (const float4*)g_P;
    const float4* EF4 = (const float4*)edge_feat;

    const int nTiles = (E + E_TILE - 1) / E_TILE;
    for (int t = blockIdx.x; t < nTiles; t += gridDim.x) {
        const int base = t * E_TILE;
        __syncthreads();   // protects presum/msg + ds reuse across tiles

        // ---- gather ----
        #pragma unroll 2
        for (int i = 0; i < 8; i++) {
            int el  = warp * 16 + i * 2 + half;
            int eg  = base + el;
            int egc = eg < E ? eg : E - 1;
            int s = src[egc];
            int d = dst[egc];
            float4 ps = P4[(long)s * 32 + j];
            float4 pd = P4[(long)d * 32 + 16 + j];
            float4 sum = make_float4(ps.x + pd.x, ps.y + pd.y,
                                     ps.z + pd.z, ps.w + pd.w);
            *(float4*)(presum + el * PSTR + j * 4) = sum;
            if (j < 4) {
                *(float4*)(fsmall + el * FSSTR + j * 4) = EF4[(long)egc * 4 + j];
            } else if (j == 4) {
                float cx = coord[s * 3 + 0] - coord[d * 3 + 0];
                float cy = coord[s * 3 + 1] - coord[d * 3 + 1];
                float cz = coord[s * 3 + 2] - coord[d * 3 + 2];
                fsmall[el * FSSTR + 16] = cx * cx + cy * cy + cz * cz;
            } else if (j < 12) {
                fsmall[el * FSSTR + 17 + (j - 5)] = 0.0f;   // pad 17..23
            } else if (j == 12) {
                ds[el] = d;
            }
        }
        __syncthreads();

        // ---- GEMM1: [128,24]@[24,64] ----
        float d1[2][4][4];
        #pragma unroll
        for (int mi = 0; mi < 2; mi++)
            #pragma unroll
            for (int nj = 0; nj < 4; nj++)
                #pragma unroll
                for (int q = 0; q < 4; q++) d1[mi][nj][q] = 0.0f;

        const unsigned* w1u = (const unsigned*)W1s;
        #pragma unroll
        for (int ks = 0; ks < 3; ks++) {
            const int kk = ks * 8;
            unsigned a[2][4];
            #pragma unroll
            for (int mi = 0; mi < 2; mi++) {
                int r0 = mrow + mi * 16 + gid;
                const float* fp  = fsmall + r0 * FSSTR + kk + tig;
                const float* fp8 = fp + 8 * FSSTR;
                a[mi][0] = f2tf(fp[0]);
                a[mi][1] = f2tf(fp8[0]);
                a[mi][2] = f2tf(fp[4]);
                a[mi][3] = f2tf(fp8[4]);
            }
            #pragma unroll
            for (int nj = 0; nj < 4; nj++) {
                int n = nbase + nj * 8 + gid;
                unsigned bb[2];
                bb[0] = w1u[(kk + tig) * WSTR + n];
                bb[1] = w1u[(kk + tig + 4) * WSTR + n];
                mma_tf32(d1[0][nj], a[0], bb);
                mma_tf32(d1[1][nj], a[1], bb);
            }
        }

        // ---- epilogue1: m = tf32(silu(d1 + presum + b1)) ----
        #pragma unroll
        for (int mi = 0; mi < 2; mi++) {
            int r0 = mrow + mi * 16 + gid;
            #pragma unroll
            for (int nj = 0; nj < 4; nj++) {
                int c0 = nbase + nj * 8 + tig * 2;
                float bb0 = b1s[c0], bb1 = b1s[c0 + 1];
                m[r0 * MSTR + c0] = __uint_as_float(f2tf(
                    silu(d1[mi][nj][0] + presum[r0 * PSTR + c0] + bb0)));
                m[r0 * MSTR + c0 + 1] = __uint_as_float(f2tf(
                    silu(d1[mi][nj][1] + presum[r0 * PSTR + c0 + 1] + bb1)));
                m[(r0 + 8) * MSTR + c0] = __uint_as_float(f2tf(
                    silu(d1[mi][nj][2] + presum[(r0 + 8) * PSTR + c0] + bb0)));
                m[(r0 + 8) * MSTR + c0 + 1] = __uint_as_float(f2tf(
                    silu(d1[mi][nj][3] + presum[(r0 + 8) * PSTR + c0 + 1] + bb1)));
            }
        }
        __syncthreads();   // m complete; presum reads done (msg may overwrite)

        // ---- GEMM2: [128,64]@[64,64] ----
        float d2[2][4][4];
        #pragma unroll
        for (int mi = 0; mi < 2; mi++)
            #pragma unroll
            for (int nj = 0; nj < 4; nj++)
                #pragma unroll
                for (int q = 0; q < 4; q++) d2[mi][nj][q] = 0.0f;

        const unsigned* msu = (const unsigned*)m;
        const unsigned* w2u = (const unsigned*)W2s;
        #pragma unroll 2
        for (int ks = 0; ks < 8; ks++) {
            const int kk = ks * 8;
            unsigned a[2][4];
            #pragma unroll
            for (int mi = 0; mi < 2; mi++) {
                int r0 = mrow + mi * 16 + gid;
                const unsigned* mp  = msu + r0 * MSTR + kk + tig;
                const unsigned* mp8 = mp + 8 * MSTR;
                a[mi][0] = mp[0];
                a[mi][1] = mp8[0];
                a[mi][2] = mp[4];
                a[mi][3] = mp8[4];
            }
            #pragma unroll
            for (int nj = 0; nj < 4; nj++) {
                int n = nbase + nj * 8 + gid;
                unsigned bb[2];
                bb[0] = w2u[(kk + tig) * WSTR + n];
                bb[1] = w2u[(kk + tig + 4) * WSTR + n];
                mma_tf32(d2[0][nj], a[0], bb);
                mma_tf32(d2[1][nj], a[1], bb);
            }
        }

        // ---- epilogue2: msg = silu(d2 + b2) ----
        #pragma unroll
        for (int mi = 0; mi < 2; mi++) {
            int r0 = mrow + mi * 16 + gid;
            #pragma unroll
            for (int nj = 0; nj < 4; nj++) {
                int c0 = nbase + nj * 8 + tig * 2;
                float bb0 = b2s[c0], bb1 = b2s[c0 + 1];
                msg[r0 * PSTR + c0]           = silu(d2[mi][nj][0] + bb0);
                msg[r0 * PSTR + c0 + 1]       = silu(d2[mi][nj][1] + bb1);
                msg[(r0 + 8) * PSTR + c0]     = silu(d2[mi][nj][2] + bb0);
                msg[(r0 + 8) * PSTR + c0 + 1] = silu(d2[mi][nj][3] + bb1);
            }
        }
        __syncthreads();

        // ---- scatter: red.v4 into g_hneigh ----
        #pragma unroll 2
        for (int i = 0; i < 8; i++) {
            int r = warp * 16 + i * 2 + half;
            int c = j * 4;
            if (base + r < E) {
                float4 v = *(const float4*)(msg + r * PSTR + c);
                red_v4(g_hneigh + (long)ds[r] * HH + c, v);
            }
        }
    }
}

// ---------------------------------------------------------------------------
// Node kernel: tf32 mma, unchanged from R3. z=[node_feat|h_neigh] (K=128).
// ---------------------------------------------------------------------------
#define N_TILE 256
#define ZSTR   132
#define THREADS 512

__global__ void __launch_bounds__(THREADS, 1)
node_kernel(const float* __restrict__ node_feat,
            const float* __restrict__ Wn1,
            const float* __restrict__ bn1,
            const float* __restrict__ Wn2,
            const float* __restrict__ bn2,
            float* __restrict__ out,
            int N)
{
    extern __shared__ float sm[];
    float* zs  = sm;                        // 256*132 (m aliases, stride 68)
    float* W1s = zs + N_TILE * ZSTR;        // 128*72
    float* W2s = W1s + 128 * WSTR;          // 64*72
    float* b1s = W2s + HH * WSTR;
    float* b2s = b1s + HH;

    const int tid = threadIdx.x;

    for (int i = tid; i < 128 * HH; i += THREADS) {
        int r = i / HH, c = i % HH;
        W1s[r * WSTR + c] = __uint_as_float(f2tf(Wn1[i]));
    }
    for (int i = tid; i < HH * DD; i += THREADS) {
        int r = i / DD, c = i % DD;
        W2s[r * WSTR + c] = __uint_as_float(f2tf(Wn2[i]));
    }
    if (tid < HH) { b1s[tid] = bn1[tid]; b2s[tid] = bn2[tid]; }

    const int warp = tid >> 5;
    const int lane = tid & 31;
    const int gid  = lane >> 2;
    const int tig  = lane & 3;
    const int mrow  = (warp & 7) * 32;
    const int nbase = (warp >> 3) * 32;

    const float4* nf4 = (const float4*)node_feat;
    const float4* hn4 = (const float4*)g_hneigh;

    const int nTiles = (N + N_TILE - 1) / N_TILE;
    for (int t = blockIdx.x; t < nTiles; t += gridDim.x) {
        const int base = t * N_TILE;
        __syncthreads();

        for (int idx = tid; idx < N_TILE * 32; idx += THREADS) {
            int nl = idx >> 5, c = idx & 31;
            int n = base + nl;
            if (n >= N) n = N - 1;
            float4 v = (c < 16) ? nf4[(long)n * 16 + c]
                                : hn4[(long)n * 16 + (c - 16)];
            ((float4*)(zs + nl * ZSTR))[c] = v;
        }
        __syncthreads();

        float d1[2][4][4];
        #pragma unroll
        for (int mi = 0; mi < 2; mi++)
            #pragma unroll
            for (int nj = 0; nj < 4; nj++)
                #pragma unroll
                for (int q = 0; q < 4; q++) d1[mi][nj][q] = 0.0f;

        const unsigned* w1u = (const unsigned*)W1s;
        for (int ks = 0; ks < 16; ks++) {
            const int kk = ks * 8;
            unsigned a[2][4];
            #pragma unroll
            for (int mi = 0; mi < 2; mi++) {
                int r0 = mrow + mi * 16 + gid;
                const float* fp  = zs + r0 * ZSTR + kk + tig;
                const float* fp8 = fp + 8 * ZSTR;
                a[mi][0] = f2tf(fp[0]);
                a[mi][1] = f2tf(fp8[0]);
                a[mi][2] = f2tf(fp[4]);
                a[mi][3] = f2tf(fp8[4]);
            }
            #pragma unroll
            for (int nj = 0; nj < 4; nj++) {
                int n = nbase + nj * 8 + gid;
                unsigned bb[2];
                bb[0] = w1u[(kk + tig) * WSTR + n];
                bb[1] = w1u[(kk + tig + 4) * WSTR + n];
                mma_tf32(d1[0][nj], a[0], bb);
                mma_tf32(d1[1][nj], a[1], bb);
            }
        }
        __syncthreads();

        #pragma unroll
        for (int mi = 0; mi < 2; mi++) {
            int r0 = mrow + mi * 16 + gid;
            #pragma unroll
            for (int nj = 0; nj < 4; nj++) {
                int c0 = nbase + nj * 8 + tig * 2;
                float bb0 = b1s[c0], bb1 = b1s[c0 + 1];
                zs[r0 * MSTR + c0]
                    = __uint_as_float(f2tf(silu(d1[mi][nj][0] + bb0)));
                zs[r0 * MSTR + c0 + 1]
                    = __uint_as_float(f2tf(silu(d1[mi][nj][1] + bb1)));
                zs[(r0 + 8) * MSTR + c0]
                    = __uint_as_float(f2tf(silu(d1[mi][nj][2] + bb0)));
                zs[(r0 + 8) * MSTR + c0 + 1]
                    = __uint_as_float(f2tf(silu(d1[mi][nj][3] + bb1)));
            }
        }
        __syncthreads();

        float d2[2][4][4];
        #pragma unroll
        for (int mi = 0; mi < 2; mi++)
            #pragma unroll
            for (int nj = 0; nj < 4; nj++)
                #pragma unroll
                for (int q = 0; q < 4; q++) d2[mi][nj][q] = 0.0f;

        const unsigned* msu = (const unsigned*)zs;
        const unsigned* w2u = (const unsigned*)W2s;
        for (int ks = 0; ks < 8; ks++) {
            const int kk = ks * 8;
            unsigned a[2][4];
            #pragma unroll
            for (int mi = 0; mi < 2; mi++) {
                int r0 = mrow + mi * 16 + gid;
                const unsigned* mp  = msu + r0 * MSTR + kk + tig;
                const unsigned* mp8 = mp + 8 * MSTR;
                a[mi][0] = mp[0];
                a[mi][1] = mp8[0];
                a[mi][2] = mp[4];
                a[mi][3] = mp8[4];
            }
            #pragma unroll
            for (int nj = 0; nj < 4; nj++) {
                int n = nbase + nj * 8 + gid;
                unsigned bb[2];
                bb[0] = w2u[(kk + tig) * WSTR + n];
                bb[1] = w2u[(kk + tig + 4) * WSTR + n];
                mma_tf32(d2[0][nj], a[0], bb);
                mma_tf32(d2[1][nj], a[1], bb);
            }
        }

        #pragma unroll
        for (int mi = 0; mi < 2; mi++) {
            int r0 = mrow + mi * 16 + gid;
            #pragma unroll
            for (int nj = 0; nj < 4; nj++) {
                int c0 = nbase + nj * 8 + tig * 2;
                float bb0 = b2s[c0], bb1 = b2s[c0 + 1];
                int n0 = base + r0, n1 = base + r0 + 8;
                if (n0 < N)
                    *(float2*)(out + (long)n0 * DD + c0)
                        = make_float2(d2[mi][nj][0] + bb0, d2[mi][nj][1] + bb1);
                if (n1 < N)
                    *(float2*)(out + (long)n1 * DD + c0)
                        = make_float2(d2[mi][nj][2] + bb0, d2[mi][nj][3] + bb1);
            }
        }
    }
}

// ---------------------------------------------------------------------------
extern "C" void kernel_launch(void* const* d_in, const int* in_sizes, int n_in,
                              void* d_out, int out_size)
{
    const float* node_feat = (const float*)d_in[0];
    const float* coord     = (const float*)d_in[1];
    const float* edge_feat = (const float*)d_in[2];
    const int*   src       = (const int*)d_in[3];
    const int*   dst       = (const int*)d_in[4];
    const float* We1       = (const float*)d_in[5];
    const float* be1       = (const float*)d_in[6];
    const float* We2       = (const float*)d_in[7];
    const float* be2       = (const float*)d_in[8];
    const float* Wn1       = (const float*)d_in[9];
    const float* bn1       = (const float*)d_in[10];
    const float* Wn2       = (const float*)d_in[11];
    const float* bn2       = (const float*)d_in[12];
    float* out = (float*)d_out;

    const int N = in_sizes[0] / DD;
    const int E = in_sizes[3];

    const size_t smem_p =
        (size_t)(128 * ASTR + 64 * BSTR2) * sizeof(float);            // 69632
    const size_t smem_edge =
        (size_t)(K1S * WSTR + HH * WSTR + 2 * HH + E_TILE
                 + E_TILE * PSTR + E_TILE * FSSTR + E_TILE * MSTR)
        * sizeof(float);                                              // 110336
    const size_t smem_node =
        (size_t)(N_TILE * ZSTR + 128 * WSTR + HH * WSTR + 2 * HH)
        * sizeof(float);

    cudaFuncSetAttribute(p_kernel,
                         cudaFuncAttributeMaxDynamicSharedMemorySize,
                         (int)smem_p);
    cudaFuncSetAttribute(edge_kernel,
                         cudaFuncAttributeMaxDynamicSharedMemorySize,
                         (int)smem_edge);
    cudaFuncSetAttribute(node_kernel,
                         cudaFuncAttributeMaxDynamicSharedMemorySize,
                         (int)smem_node);

    int numSMs = 148;
    cudaDeviceGetAttribute(&numSMs, cudaDevAttrMultiProcessorCount, 0);

    // 1) zero scatter buffer
    int nh = N * HH;
    zero_hneigh_kernel<<<(nh + 511) / 512, 512>>>(nh);

    // 2) P = node_feat @ [W1_src | W1_dst]
    int pTiles = (N + 127) / 128;
    p_kernel<<<pTiles, 512, smem_p>>>(node_feat, We1, N);

    // 3) edge MLP + scatter (persistent, 2 CTAs/SM)
    int eTiles = (E + E_TILE - 1) / E_TILE;
    int eGrid = 2 * numSMs;
    if (eGrid > eTiles) eGrid = eTiles;
    edge_kernel<<<eGrid, ETHREADS, smem_edge>>>(
        coord, edge_feat, src, dst, We1, be1, We2, be2, E);

    // 4) node MLP
    int nTiles = (N + N_TILE - 1) / N_TILE;
    int nGrid = nTiles < numSMs ? nTiles : numSMs;
    node_kernel<<<nGrid, THREADS, smem_node>>>(
        node_feat, Wn1, bn1, Wn2, bn2, out, N);
}

// round 5
// speedup vs baseline: 5.8739x; 1.5233x over previous
#include <cuda_runtime.h>

// ---------------------------------------------------------------------------
// EGNN edge/node block, round 5.
// P[n] = [h_n@W1_src | h_n@W1_dst] precomputed (zero of g_hneigh fused into
// the same launch). Edge kernel: latency-optimized gather (batched index
// loads + front-batched LDG.128 P gather + cp.async edge_feat), tf32
// mma.sync GEMMs, red.v4 scatter. 256 thr, 2 CTAs/SM.
// N=50000, E=800000, D=64, H=64, EF=16.
// ---------------------------------------------------------------------------

#define NN      50000
#define DD      64
#define HH      64
#define E_TILE  128
#define WSTR    72     // weight row stride (72%32=8, conflict-free)
#define PSTR    68     // presum/msg row stride (68%32=4)
#define FSSTR   28     // fsmall row stride (28%32=28, conflict-free)
#define MSTR    68     // m row stride
#define K1S     24     // padded small-K of edge layer 1 (3 k-steps)

__device__ float g_hneigh[NN * HH];
__device__ float g_P[NN * 128];   // [n][0:64]=h@W1_src, [64:128]=h@W1_dst

__device__ __forceinline__ float silu(float x) {
    return x / (1.0f + __expf(-x));
}
__device__ __forceinline__ unsigned f2tf(float x) {
    unsigned r;
    asm("cvt.rna.tf32.f32 %0, %1;" : "=r"(r) : "f"(x));
    return r;
}
__device__ __forceinline__ void mma_tf32(float d[4], const unsigned a[4],
                                         const unsigned b[2]) {
    asm volatile(
        "mma.sync.aligned.m16n8k8.row.col.f32.tf32.tf32.f32 "
        "{%0,%1,%2,%3}, {%4,%5,%6,%7}, {%8,%9}, {%0,%1,%2,%3};"
        : "+f"(d[0]), "+f"(d[1]), "+f"(d[2]), "+f"(d[3])
        : "r"(a[0]), "r"(a[1]), "r"(a[2]), "r"(a[3]), "r"(b[0]), "r"(b[1]));
}
__device__ __forceinline__ void red_v4(float* p, float4 v) {
    asm volatile("red.global.add.v4.f32 [%0], {%1,%2,%3,%4};"
                 :: "l"(p), "f"(v.x), "f"(v.y), "f"(v.z), "f"(v.w) : "memory");
}
__device__ __forceinline__ void cp16(unsigned saddr, const void* g) {
    asm volatile("cp.async.ca.shared.global [%0], [%1], 16;"
                 :: "r"(saddr), "l"(g));
}

// ---------------------------------------------------------------------------
// P kernel (+ fused zeroing of g_hneigh by trailing blocks).
// P = node_feat @ [W1_src | W1_dst]  ([N,64]@[64,128], tf32 mma)
// ---------------------------------------------------------------------------
#define ASTR  68
#define BSTR2 136

__global__ void __launch_bounds__(512, 1)
p_kernel(const float* __restrict__ node_feat,
         const float* __restrict__ We1,
         int N, int pTiles)
{
    const int tid = threadIdx.x;

    if ((int)blockIdx.x >= pTiles) {
        // zeroing block for g_hneigh
        const int zb = blockIdx.x - pTiles;
        float4* h4 = (float4*)g_hneigh;
        const int total4 = NN * HH / 4;
        for (int i = zb * 512 + tid; i < total4; i += (gridDim.x - pTiles) * 512)
            h4[i] = make_float4(0.f, 0.f, 0.f, 0.f);
        return;
    }

    extern __shared__ float sm[];
    float* As = sm;                 // 128*68
    float* Bs = As + 128 * ASTR;    // 64*136

    for (int i = tid; i < 64 * 128; i += 512) {
        int k = i >> 7, j = i & 127;
        float v = (j < 64) ? We1[k * HH + j] : We1[(64 + k) * HH + (j - 64)];
        Bs[k * BSTR2 + j] = __uint_as_float(f2tf(v));
    }
    const int base = blockIdx.x * 128;
    const float4* nf4 = (const float4*)node_feat;
    for (int idx = tid; idx < 128 * 16; idx += 512) {
        int r = idx >> 4, c = idx & 15;
        int n = base + r;
        if (n >= N) n = N - 1;
        ((float4*)(As + r * ASTR))[c] = nf4[(long)n * 16 + c];
    }
    __syncthreads();

    const int warp = tid >> 5, lane = tid & 31;
    const int gid = lane >> 2, tig = lane & 3;
    const int mrow  = (warp & 3) * 32;
    const int nbase = (warp >> 2) * 32;

    float d[2][4][4];
    #pragma unroll
    for (int mi = 0; mi < 2; mi++)
        #pragma unroll
        for (int nj = 0; nj < 4; nj++)
            #pragma unroll
            for (int q = 0; q < 4; q++) d[mi][nj][q] = 0.0f;

    const unsigned* bu = (const unsigned*)Bs;
    #pragma unroll
    for (int ks = 0; ks < 8; ks++) {
        const int kk = ks * 8;
        unsigned a[2][4];
        #pragma unroll
        for (int mi = 0; mi < 2; mi++) {
            int r0 = mrow + mi * 16 + gid;
            const float* fp  = As + r0 * ASTR + kk + tig;
            const float* fp8 = fp + 8 * ASTR;
            a[mi][0] = f2tf(fp[0]);
            a[mi][1] = f2tf(fp8[0]);
            a[mi][2] = f2tf(fp[4]);
            a[mi][3] = f2tf(fp8[4]);
        }
        #pragma unroll
        for (int nj = 0; nj < 4; nj++) {
            int n = nbase + nj * 8 + gid;
            unsigned bb[2];
            bb[0] = bu[(kk + tig) * BSTR2 + n];
            bb[1] = bu[(kk + tig + 4) * BSTR2 + n];
            mma_tf32(d[0][nj], a[0], bb);
            mma_tf32(d[1][nj], a[1], bb);
        }
    }
    #pragma unroll
    for (int mi = 0; mi < 2; mi++) {
        int r0 = mrow + mi * 16 + gid;
        #pragma unroll
        for (int nj = 0; nj < 4; nj++) {
            int c0 = nbase + nj * 8 + tig * 2;
            int n0 = base + r0, n1 = base + r0 + 8;
            if (n0 < N)
                *(float2*)(g_P + (long)n0 * 128 + c0)
                    = make_float2(d[mi][nj][0], d[mi][nj][1]);
            if (n1 < N)
                *(float2*)(g_P + (long)n1 * 128 + c0)
                    = make_float2(d[mi][nj][2], d[mi][nj][3]);
        }
    }
}

// ---------------------------------------------------------------------------
// Edge kernel. Per tile of 128 edges:
//   gather: presum[e] = P[src][0:64] + P[dst][64:128] (batched LDG.128),
//           fsmall[e] = [edge_feat(16, cp.async), radial(16 lanes)], ds[e]
//   GEMM1 (3 ksteps): m = tf32(silu(fsmall@W1small + presum + b1))
//   GEMM2 (8 ksteps, full unroll): msg = silu(m@W2 + b2)
//   scatter: red.v4 msg into g_hneigh[dst]
// 256 threads (8 warps), persistent, 2 CTAs/SM.
// ---------------------------------------------------------------------------
#define ETHREADS 256

__global__ void __launch_bounds__(ETHREADS, 2)
edge_kernel(const float* __restrict__ coord,
            const float* __restrict__ edge_feat,
            const int*   __restrict__ src,
            const int*   __restrict__ dst,
            const float* __restrict__ We1,
            const float* __restrict__ be1,
            const float* __restrict__ We2,
            const float* __restrict__ be2,
            int E)
{
    extern __shared__ float sm[];
    float* W1s    = sm;                      // 24*72
    float* W2s    = W1s + K1S * WSTR;        // 64*72
    float* b1s    = W2s + HH * WSTR;         // 64
    float* b2s    = b1s + HH;                // 64
    int*   ds     = (int*)(b2s + HH);        // 128
    float* presum = (float*)(ds + E_TILE);   // 128*68 (msg aliases)
    float* fsmall = presum + E_TILE * PSTR;  // 128*28
    float* m      = fsmall + E_TILE * FSSTR; // 128*68
    float* msg    = presum;                  // alias

    const int tid = threadIdx.x;

    // W1small rows: 0-15 = edge_feat rows (orig 129-144), 16 = radial (128)
    for (int i = tid; i < K1S * HH; i += ETHREADS) {
        int r = i / HH, c = i % HH;
        float v = 0.0f;
        if (r < 16)       v = We1[(129 + r) * HH + c];
        else if (r == 16) v = We1[128 * HH + c];
        W1s[r * WSTR + c] = __uint_as_float(f2tf(v));
    }
    for (int i = tid; i < HH * HH; i += ETHREADS) {
        int r = i / HH, c = i % HH;
        W2s[r * WSTR + c] = __uint_as_float(f2tf(We2[i]));
    }
    if (tid < HH) { b1s[tid] = be1[tid]; b2s[tid] = be2[tid]; }
    // zero the constant pad columns of fsmall ONCE (cols 17..27)
    for (int i = tid; i < E_TILE * 11; i += ETHREADS) {
        int r = i / 11, c = 17 + (i % 11);
        fsmall[r * FSSTR + c] = 0.0f;
    }

    const int warp = tid >> 5;
    const int lane = tid & 31;
    const int gid  = lane >> 2;
    const int tig  = lane & 3;
    const int mrow  = (warp & 3) * 32;
    const int nbase = (warp >> 2) * 32;
    const int half  = lane >> 4;            // 0/1
    const int j     = lane & 15;            // 0..15

    const float4* P4 = (const float4*)g_P;
    const unsigned fsb =
        (unsigned)__cvta_generic_to_shared(fsmall);

    const int nTiles = (E + E_TILE - 1) / E_TILE;
    for (int t = blockIdx.x; t < nTiles; t += gridDim.x) {
        const int base = t * E_TILE;
        __syncthreads();   // protects presum/msg/ds reuse across tiles

        // ================= GATHER (latency-batched) =================
        const int eb = base + warp * 16;     // this warp's 16 edges

        // 1) all 16 src + 16 dst indices: 2 coalesced LDG.32
        int egi = eb + j; if (egi >= E) egi = E - 1;
        const int myidx = (lane < 16) ? src[egi] : dst[egi];

        // 2) edge_feat via cp.async (2 rounds x 8 edges x 4 chunks)
        #pragma unroll
        for (int r = 0; r < 2; r++) {
            int el = warp * 16 + r * 8 + (lane >> 2);
            int eg = base + el; if (eg >= E) eg = E - 1;
            int c = lane & 3;
            cp16(fsb + el * (FSSTR * 4) + c * 16,
                 edge_feat + (long)eg * 16 + c * 4);
        }
        asm volatile("cp.async.commit_group;");

        // 3) P gather: issue ALL 16 LDG.128 before any consume
        float4 ps[8], pd[8];
        #pragma unroll
        for (int i = 0; i < 8; i++) {
            int el = i * 2 + half;
            int s = __shfl_sync(0xffffffffu, myidx, el);
            int d = __shfl_sync(0xffffffffu, myidx, 16 + el);
            ps[i] = P4[(long)s * 32 + j];
            pd[i] = P4[(long)d * 32 + 16 + j];
        }

        // 4) radial (lanes 0..15, one edge each) + ds (lanes 16..31)
        {
            int s_r = __shfl_sync(0xffffffffu, myidx, j);
            int d_r = __shfl_sync(0xffffffffu, myidx, 16 + j);
            if (lane < 16) {
                float cx = coord[s_r * 3 + 0] - coord[d_r * 3 + 0];
                float cy = coord[s_r * 3 + 1] - coord[d_r * 3 + 1];
                float cz = coord[s_r * 3 + 2] - coord[d_r * 3 + 2];
                fsmall[(warp * 16 + j) * FSSTR + 16]
                    = cx * cx + cy * cy + cz * cz;
            } else {
                ds[warp * 16 + j] = d_r;
            }
        }

        // 5) combine + store presum
        #pragma unroll
        for (int i = 0; i < 8; i++) {
            int el = warp * 16 + i * 2 + half;
            float4 v = make_float4(ps[i].x + pd[i].x, ps[i].y + pd[i].y,
                                   ps[i].z + pd[i].z, ps[i].w + pd[i].w);
            *(float4*)(presum + el * PSTR + j * 4) = v;
        }

        asm volatile("cp.async.wait_group 0;");
        __syncthreads();

        // ================= GEMM1: [128,24]@[24,64] =================
        float d1[2][4][4];
        #pragma unroll
        for (int mi = 0; mi < 2; mi++)
            #pragma unroll
            for (int nj = 0; nj < 4; nj++)
                #pragma unroll
                for (int q = 0; q < 4; q++) d1[mi][nj][q] = 0.0f;

        const unsigned* w1u = (const unsigned*)W1s;
        #pragma unroll
        for (int ks = 0; ks < 3; ks++) {
            const int kk = ks * 8;
            unsigned a[2][4];
            #pragma unroll
            for (int mi = 0; mi < 2; mi++) {
                int r0 = mrow + mi * 16 + gid;
                const float* fp  = fsmall + r0 * FSSTR + kk + tig;
                const float* fp8 = fp + 8 * FSSTR;
                a[mi][0] = f2tf(fp[0]);
                a[mi][1] = f2tf(fp8[0]);
                a[mi][2] = f2tf(fp[4]);
                a[mi][3] = f2tf(fp8[4]);
            }
            #pragma unroll
            for (int nj = 0; nj < 4; nj++) {
                int n = nbase + nj * 8 + gid;
                unsigned bb[2];
                bb[0] = w1u[(kk + tig) * WSTR + n];
                bb[1] = w1u[(kk + tig + 4) * WSTR + n];
                mma_tf32(d1[0][nj], a[0], bb);
                mma_tf32(d1[1][nj], a[1], bb);
            }
        }

        // ---- epilogue1: m = tf32(silu(d1 + presum + b1)) ----
        #pragma unroll
        for (int mi = 0; mi < 2; mi++) {
            int r0 = mrow + mi * 16 + gid;
            #pragma unroll
            for (int nj = 0; nj < 4; nj++) {
                int c0 = nbase + nj * 8 + tig * 2;
                float bb0 = b1s[c0], bb1 = b1s[c0 + 1];
                m[r0 * MSTR + c0] = __uint_as_float(f2tf(
                    silu(d1[mi][nj][0] + presum[r0 * PSTR + c0] + bb0)));
                m[r0 * MSTR + c0 + 1] = __uint_as_float(f2tf(
                    silu(d1[mi][nj][1] + presum[r0 * PSTR + c0 + 1] + bb1)));
                m[(r0 + 8) * MSTR + c0] = __uint_as_float(f2tf(
                    silu(d1[mi][nj][2] + presum[(r0 + 8) * PSTR + c0] + bb0)));
                m[(r0 + 8) * MSTR + c0 + 1] = __uint_as_float(f2tf(
                    silu(d1[mi][nj][3] + presum[(r0 + 8) * PSTR + c0 + 1] + bb1)));
            }
        }
        __syncthreads();   // m complete; presum reads done

        // ================= GEMM2: [128,64]@[64,64] =================
        float d2[2][4][4];
        #pragma unroll
        for (int mi = 0; mi < 2; mi++)
            #pragma unroll
            for (int nj = 0; nj < 4; nj++)
                #pragma unroll
                for (int q = 0; q < 4; q++) d2[mi][nj][q] = 0.0f;

        const unsigned* msu = (const unsigned*)m;
        const unsigned* w2u = (const unsigned*)W2s;
        #pragma unroll
        for (int ks = 0; ks < 8; ks++) {
            const int kk = ks * 8;
            unsigned a[2][4];
            #pragma unroll
            for (int mi = 0; mi < 2; mi++) {
                int r0 = mrow + mi * 16 + gid;
                const unsigned* mp  = msu + r0 * MSTR + kk + tig;
                const unsigned* mp8 = mp + 8 * MSTR;
                a[mi][0] = mp[0];
                a[mi][1] = mp8[0];
                a[mi][2] = mp[4];
                a[mi][3] = mp8[4];
            }
            #pragma unroll
            for (int nj = 0; nj < 4; nj++) {
                int n = nbase + nj * 8 + gid;
                unsigned bb[2];
                bb[0] = w2u[(kk + tig) * WSTR + n];
                bb[1] = w2u[(kk + tig + 4) * WSTR + n];
                mma_tf32(d2[0][nj], a[0], bb);
                mma_tf32(d2[1][nj], a[1], bb);
            }
        }

        // ---- epilogue2: msg = silu(d2 + b2) ----
        #pragma unroll
        for (int mi = 0; mi < 2; mi++) {
            int r0 = mrow + mi * 16 + gid;
            #pragma unroll
            for (int nj = 0; nj < 4; nj++) {
                int c0 = nbase + nj * 8 + tig * 2;
                float bb0 = b2s[c0], bb1 = b2s[c0 + 1];
                msg[r0 * PSTR + c0]           = silu(d2[mi][nj][0] + bb0);
                msg[r0 * PSTR + c0 + 1]       = silu(d2[mi][nj][1] + bb1);
                msg[(r0 + 8) * PSTR + c0]     = silu(d2[mi][nj][2] + bb0);
                msg[(r0 + 8) * PSTR + c0 + 1] = silu(d2[mi][nj][3] + bb1);
            }
        }
        __syncthreads();

        // ---- scatter: red.v4 into g_hneigh ----
        #pragma unroll
        for (int i = 0; i < 8; i++) {
            int r = warp * 16 + i * 2 + half;
            int c = j * 4;
            if (base + r < E) {
                float4 v = *(const float4*)(msg + r * PSTR + c);
                red_v4(g_hneigh + (long)ds[r] * HH + c, v);
            }
        }
    }
}

// ---------------------------------------------------------------------------
// Node kernel: tf32 mma. z=[node_feat|h_neigh] (K=128).
// ---------------------------------------------------------------------------
#define N_TILE 256
#define ZSTR   132
#define THREADS 512

__global__ void __launch_bounds__(THREADS, 1)
node_kernel(const float* __restrict__ node_feat,
            const float* __restrict__ Wn1,
            const float* __restrict__ bn1,
            const float* __restrict__ Wn2,
            const float* __restrict__ bn2,
            float* __restrict__ out,
            int N)
{
    extern __shared__ float sm[];
    float* zs  = sm;                        // 256*132 (m aliases, stride 68)
    float* W1s = zs + N_TILE * ZSTR;        // 128*72
    float* W2s = W1s + 128 * WSTR;          // 64*72
    float* b1s = W2s + HH * WSTR;
    float* b2s = b1s + HH;

    const int tid = threadIdx.x;

    for (int i = tid; i < 128 * HH; i += THREADS) {
        int r = i / HH, c = i % HH;
        W1s[r * WSTR + c] = __uint_as_float(f2tf(Wn1[i]));
    }
    for (int i = tid; i < HH * DD; i += THREADS) {
        int r = i / DD, c = i % DD;
        W2s[r * WSTR + c] = __uint_as_float(f2tf(Wn2[i]));
    }
    if (tid < HH) { b1s[tid] = bn1[tid]; b2s[tid] = bn2[tid]; }

    const int warp = tid >> 5;
    const int lane = tid & 31;
    const int gid  = lane >> 2;
    const int tig  = lane & 3;
    const int mrow  = (warp & 7) * 32;
    const int nbase = (warp >> 3) * 32;

    const float4* nf4 = (const float4*)node_feat;
    const float4* hn4 = (const float4*)g_hneigh;

    const int nTiles = (N + N_TILE - 1) / N_TILE;
    for (int t = blockIdx.x; t < nTiles; t += gridDim.x) {
        const int base = t * N_TILE;
        __syncthreads();

        for (int idx = tid; idx < N_TILE * 32; idx += THREADS) {
            int nl = idx >> 5, c = idx & 31;
            int n = base + nl;
            if (n >= N) n = N - 1;
            float4 v = (c < 16) ? nf4[(long)n * 16 + c]
                                : hn4[(long)n * 16 + (c - 16)];
            ((float4*)(zs + nl * ZSTR))[c] = v;
        }
        __syncthreads();

        float d1[2][4][4];
        #pragma unroll
        for (int mi = 0; mi < 2; mi++)
            #pragma unroll
            for (int nj = 0; nj < 4; nj++)
                #pragma unroll
                for (int q = 0; q < 4; q++) d1[mi][nj][q] = 0.0f;

        const unsigned* w1u = (const unsigned*)W1s;
        #pragma unroll 4
        for (int ks = 0; ks < 16; ks++) {
            const int kk = ks * 8;
            unsigned a[2][4];
            #pragma unroll
            for (int mi = 0; mi < 2; mi++) {
                int r0 = mrow + mi * 16 + gid;
                const float* fp  = zs + r0 * ZSTR + kk + tig;
                const float* fp8 = fp + 8 * ZSTR;
                a[mi][0] = f2tf(fp[0]);
                a[mi][1] = f2tf(fp8[0]);
                a[mi][2] = f2tf(fp[4]);
                a[mi][3] = f2tf(fp8[4]);
            }
            #pragma unroll
            for (int nj = 0; nj < 4; nj++) {
                int n = nbase + nj * 8 + gid;
                unsigned bb[2];
                bb[0] = w1u[(kk + tig) * WSTR + n];
                bb[1] = w1u[(kk + tig + 4) * WSTR + n];
                mma_tf32(d1[0][nj], a[0], bb);
                mma_tf32(d1[1][nj], a[1], bb);
            }
        }
        __syncthreads();

        #pragma unroll
        for (int mi = 0; mi < 2; mi++) {
            int r0 = mrow + mi * 16 + gid;
            #pragma unroll
            for (int nj = 0; nj < 4; nj++) {
                int c0 = nbase + nj * 8 + tig * 2;
                float bb0 = b1s[c0], bb1 = b1s[c0 + 1];
                zs[r0 * MSTR + c0]
                    = __uint_as_float(f2tf(silu(d1[mi][nj][0] + bb0)));
                zs[r0 * MSTR + c0 + 1]
                    = __uint_as_float(f2tf(silu(d1[mi][nj][1] + bb1)));
                zs[(r0 + 8) * MSTR + c0]
                    = __uint_as_float(f2tf(silu(d1[mi][nj][2] + bb0)));
                zs[(r0 + 8) * MSTR + c0 + 1]
                    = __uint_as_float(f2tf(silu(d1[mi][nj][3] + bb1)));
            }
        }
        __syncthreads();

        float d2[2][4][4];
        #pragma unroll
        for (int mi = 0; mi < 2; mi++)
            #pragma unroll
            for (int nj = 0; nj < 4; nj++)
                #pragma unroll
                for (int q = 0; q < 4; q++) d2[mi][nj][q] = 0.0f;

        const unsigned* msu = (const unsigned*)zs;
        const unsigned* w2u = (const unsigned*)W2s;
        #pragma unroll
        for (int ks = 0; ks < 8; ks++) {
            const int kk = ks * 8;
            unsigned a[2][4];
            #pragma unroll
            for (int mi = 0; mi < 2; mi++) {
                int r0 = mrow + mi * 16 + gid;
                const unsigned* mp  = msu + r0 * MSTR + kk + tig;
                const unsigned* mp8 = mp + 8 * MSTR;
                a[mi][0] = mp[0];
                a[mi][1] = mp8[0];
                a[mi][2] = mp[4];
                a[mi][3] = mp8[4];
            }
            #pragma unroll
            for (int nj = 0; nj < 4; nj++) {
                int n = nbase + nj * 8 + gid;
                unsigned bb[2];
                bb[0] = w2u[(kk + tig) * WSTR + n];
                bb[1] = w2u[(kk + tig + 4) * WSTR + n];
                mma_tf32(d2[0][nj], a[0], bb);
                mma_tf32(d2[1][nj], a[1], bb);
            }
        }

        #pragma unroll
        for (int mi = 0; mi < 2; mi++) {
            int r0 = mrow + mi * 16 + gid;
            #pragma unroll
            for (int nj = 0; nj < 4; nj++) {
                int c0 = nbase + nj * 8 + tig * 2;
                float bb0 = b2s[c0], bb1 = b2s[c0 + 1];
                int n0 = base + r0, n1 = base + r0 + 8;
                if (n0 < N)
                    *(float2*)(out + (long)n0 * DD + c0)
                        = make_float2(d2[mi][nj][0] + bb0, d2[mi][nj][1] + bb1);
                if (n1 < N)
                    *(float2*)(out + (long)n1 * DD + c0)
                        = make_float2(d2[mi][nj][2] + bb0, d2[mi][nj][3] + bb1);
            }
        }
    }
}

// ---------------------------------------------------------------------------
extern "C" void kernel_launch(void* const* d_in, const int* in_sizes, int n_in,
                              void* d_out, int out_size)
{
    const float* node_feat = (const float*)d_in[0];
    const float* coord     = (const float*)d_in[1];
    const float* edge_feat = (const float*)d_in[2];
    const int*   src       = (const int*)d_in[3];
    const int*   dst       = (const int*)d_in[4];
    const float* We1       = (const float*)d_in[5];
    const float* be1       = (const float*)d_in[6];
    const float* We2       = (const float*)d_in[7];
    const float* be2       = (const float*)d_in[8];
    const float* Wn1       = (const float*)d_in[9];
    const float* bn1       = (const float*)d_in[10];
    const float* Wn2       = (const float*)d_in[11];
    const float* bn2       = (const float*)d_in[12];
    float* out = (float*)d_out;

    const int N = in_sizes[0] / DD;
    const int E = in_sizes[3];

    const size_t smem_p =
        (size_t)(128 * ASTR + 64 * BSTR2) * sizeof(float);
    const size_t smem_edge =
        (size_t)(K1S * WSTR + HH * WSTR + 2 * HH + E_TILE
                 + E_TILE * PSTR + E_TILE * FSSTR + E_TILE * MSTR)
        * sizeof(float);   // 110336
    const size_t smem_node =
        (size_t)(N_TILE * ZSTR + 128 * WSTR + HH * WSTR + 2 * HH)
        * sizeof(float);

    cudaFuncSetAttribute(p_kernel,
                         cudaFuncAttributeMaxDynamicSharedMemorySize,
                         (int)smem_p);
    cudaFuncSetAttribute(edge_kernel,
                         cudaFuncAttributeMaxDynamicSharedMemorySize,
                         (int)smem_edge);
    cudaFuncSetAttribute(node_kernel,
                         cudaFuncAttributeMaxDynamicSharedMemorySize,
                         (int)smem_node);

    int numSMs = 148;
    cudaDeviceGetAttribute(&numSMs, cudaDevAttrMultiProcessorCount, 0);

    // 1) P precompute + zero g_hneigh (fused grid)
    int pTiles = (N + 127) / 128;
    p_kernel<<<pTiles + 120, 512, smem_p>>>(node_feat, We1, N, pTiles);

    // 2) edge MLP + scatter (persistent, 2 CTAs/SM)
    int eTiles = (E + E_TILE - 1) / E_TILE;
    int eGrid = 2 * numSMs;
    if (eGrid > eTiles) eGrid = eTiles;
    edge_kernel<<<eGrid, ETHREADS, smem_edge>>>(
        coord, edge_feat, src, dst, We1, be1, We2, be2, E);

    // 3) node MLP
    int nTiles = (N + N_TILE - 1) / N_TILE;
    int nGrid = nTiles < numSMs ? nTiles : numSMs;
    node_kernel<<<nGrid, THREADS, smem_node>>>(
        node_feat, Wn1, bn1, Wn2, bn2, out, N);
}

// round 6
// speedup vs baseline: 6.0449x; 1.0291x over previous
#include <cuda_runtime.h>

// ---------------------------------------------------------------------------
// EGNN edge/node block, round 6.
// P[n] = [h_n@W1_src | h_n@W1_dst] precomputed (+fused zero of g_hneigh).
// Edge kernel: latency-batched gather, tf32 mma.sync GEMMs, and scatter via
// cp.reduce.async.bulk (bulk-async engine, off the LSU pipe). 256 thr,
// 2 CTAs/SM. N=50000, E=800000, D=64, H=64, EF=16.
// ---------------------------------------------------------------------------

#define NN      50000
#define DD      64
#define HH      64
#define E_TILE  128
#define WSTR    72     // weight row stride (72%32=8, conflict-free)
#define PSTR    68     // presum/msg row stride (68%32=4); 272B, 16B-aligned
#define FSSTR   28     // fsmall row stride (28%32=28, conflict-free)
#define MSTR    68     // m row stride
#define K1S     24     // padded small-K of edge layer 1 (3 k-steps)

__device__ float g_hneigh[NN * HH];
__device__ float g_P[NN * 128];   // [n][0:64]=h@W1_src, [64:128]=h@W1_dst

__device__ __forceinline__ float silu(float x) {
    return x / (1.0f + __expf(-x));
}
__device__ __forceinline__ unsigned f2tf(float x) {
    unsigned r;
    asm("cvt.rna.tf32.f32 %0, %1;" : "=r"(r) : "f"(x));
    return r;
}
__device__ __forceinline__ void mma_tf32(float d[4], const unsigned a[4],
                                         const unsigned b[2]) {
    asm volatile(
        "mma.sync.aligned.m16n8k8.row.col.f32.tf32.tf32.f32 "
        "{%0,%1,%2,%3}, {%4,%5,%6,%7}, {%8,%9}, {%0,%1,%2,%3};"
        : "+f"(d[0]), "+f"(d[1]), "+f"(d[2]), "+f"(d[3])
        : "r"(a[0]), "r"(a[1]), "r"(a[2]), "r"(a[3]), "r"(b[0]), "r"(b[1]));
}
__device__ __forceinline__ void cp16(unsigned saddr, const void* g) {
    asm volatile("cp.async.ca.shared.global [%0], [%1], 16;"
                 :: "r"(saddr), "l"(g));
}
// bulk smem->gmem add-reduce (async proxy, bulk_group completion)
__device__ __forceinline__ void bulk_red_add(float* gptr, unsigned saddr,
                                             int bytes) {
    unsigned long long g;
    asm("cvta.to.global.u64 %0, %1;" : "=l"(g) : "l"(gptr));
    asm volatile(
        "cp.reduce.async.bulk.global.shared::cta.bulk_group.add.f32 "
        "[%0], [%1], %2;"
        :: "l"(g), "r"(saddr), "r"(bytes) : "memory");
}

// ---------------------------------------------------------------------------
// P kernel (+ fused zeroing of g_hneigh by trailing blocks).
// ---------------------------------------------------------------------------
#define ASTR  68
#define BSTR2 136

__global__ void __launch_bounds__(512, 1)
p_kernel(const float* __restrict__ node_feat,
         const float* __restrict__ We1,
         int N, int pTiles)
{
    const int tid = threadIdx.x;

    if ((int)blockIdx.x >= pTiles) {
        const int zb = blockIdx.x - pTiles;
        float4* h4 = (float4*)g_hneigh;
        const int total4 = NN * HH / 4;
        for (int i = zb * 512 + tid; i < total4; i += (gridDim.x - pTiles) * 512)
            h4[i] = make_float4(0.f, 0.f, 0.f, 0.f);
        return;
    }

    extern __shared__ float sm[];
    float* As = sm;                 // 128*68
    float* Bs = As + 128 * ASTR;    // 64*136

    for (int i = tid; i < 64 * 128; i += 512) {
        int k = i >> 7, j = i & 127;
        float v = (j < 64) ? We1[k * HH + j] : We1[(64 + k) * HH + (j - 64)];
        Bs[k * BSTR2 + j] = __uint_as_float(f2tf(v));
    }
    const int base = blockIdx.x * 128;
    const float4* nf4 = (const float4*)node_feat;
    for (int idx = tid; idx < 128 * 16; idx += 512) {
        int r = idx >> 4, c = idx & 15;
        int n = base + r;
        if (n >= N) n = N - 1;
        ((float4*)(As + r * ASTR))[c] = nf4[(long)n * 16 + c];
    }
    __syncthreads();

    const int warp = tid >> 5, lane = tid & 31;
    const int gid = lane >> 2, tig = lane & 3;
    const int mrow  = (warp & 3) * 32;
    const int nbase = (warp >> 2) * 32;

    float d[2][4][4];
    #pragma unroll
    for (int mi = 0; mi < 2; mi++)
        #pragma unroll
        for (int nj = 0; nj < 4; nj++)
            #pragma unroll
            for (int q = 0; q < 4; q++) d[mi][nj][q] = 0.0f;

    const unsigned* bu = (const unsigned*)Bs;
    #pragma unroll
    for (int ks = 0; ks < 8; ks++) {
        const int kk = ks * 8;
        unsigned a[2][4];
        #pragma unroll
        for (int mi = 0; mi < 2; mi++) {
            int r0 = mrow + mi * 16 + gid;
            const float* fp  = As + r0 * ASTR + kk + tig;
            const float* fp8 = fp + 8 * ASTR;
            a[mi][0] = f2tf(fp[0]);
            a[mi][1] = f2tf(fp8[0]);
            a[mi][2] = f2tf(fp[4]);
            a[mi][3] = f2tf(fp8[4]);
        }
        #pragma unroll
        for (int nj = 0; nj < 4; nj++) {
            int n = nbase + nj * 8 + gid;
            unsigned bb[2];
            bb[0] = bu[(kk + tig) * BSTR2 + n];
            bb[1] = bu[(kk + tig + 4) * BSTR2 + n];
            mma_tf32(d[0][nj], a[0], bb);
            mma_tf32(d[1][nj], a[1], bb);
        }
    }
    #pragma unroll
    for (int mi = 0; mi < 2; mi++) {
        int r0 = mrow + mi * 16 + gid;
        #pragma unroll
        for (int nj = 0; nj < 4; nj++) {
            int c0 = nbase + nj * 8 + tig * 2;
            int n0 = base + r0, n1 = base + r0 + 8;
            if (n0 < N)
                *(float2*)(g_P + (long)n0 * 128 + c0)
                    = make_float2(d[mi][nj][0], d[mi][nj][1]);
            if (n1 < N)
                *(float2*)(g_P + (long)n1 * 128 + c0)
                    = make_float2(d[mi][nj][2], d[mi][nj][3]);
        }
    }
}

// ---------------------------------------------------------------------------
// Edge kernel. Loop per 128-edge tile:
//   stage A (disjoint from msg/ds): indices, cp.async edge_feat, P LDG regs,
//                                   radial
//   cp.async.bulk.wait_group 0 (+sync): prev tile's bulk scatter drained
//   store presum/ds; GEMM1 -> m; GEMM2 -> msg
//   scatter: cp.reduce.async.bulk per edge (async, overlaps next stage A)
// ---------------------------------------------------------------------------
#define ETHREADS 256

__global__ void __launch_bounds__(ETHREADS, 2)
edge_kernel(const float* __restrict__ coord,
            const float* __restrict__ edge_feat,
            const int*   __restrict__ src,
            const int*   __restrict__ dst,
            const float* __restrict__ We1,
            const float* __restrict__ be1,
            const float* __restrict__ We2,
            const float* __restrict__ be2,
            int E)
{
    extern __shared__ float sm[];
    float* W1s    = sm;                      // 24*72
    float* W2s    = W1s + K1S * WSTR;        // 64*72
    float* b1s    = W2s + HH * WSTR;         // 64
    float* b2s    = b1s + HH;                // 64
    int*   ds     = (int*)(b2s + HH);        // 128
    float* presum = (float*)(ds + E_TILE);   // 128*68 (msg aliases)
    float* fsmall = presum + E_TILE * PSTR;  // 128*28
    float* m      = fsmall + E_TILE * FSSTR; // 128*68
    float* msg    = presum;                  // alias

    const int tid = threadIdx.x;

    for (int i = tid; i < K1S * HH; i += ETHREADS) {
        int r = i / HH, c = i % HH;
        float v = 0.0f;
        if (r < 16)       v = We1[(129 + r) * HH + c];
        else if (r == 16) v = We1[128 * HH + c];
        W1s[r * WSTR + c] = __uint_as_float(f2tf(v));
    }
    for (int i = tid; i < HH * HH; i += ETHREADS) {
        int r = i / HH, c = i % HH;
        W2s[r * WSTR + c] = __uint_as_float(f2tf(We2[i]));
    }
    if (tid < HH) { b1s[tid] = be1[tid]; b2s[tid] = be2[tid]; }
    for (int i = tid; i < E_TILE * 11; i += ETHREADS) {
        int r = i / 11, c = 17 + (i % 11);
        fsmall[r * FSSTR + c] = 0.0f;        // constant K-pad, written once
    }

    const int warp = tid >> 5;
    const int lane = tid & 31;
    const int gid  = lane >> 2;
    const int tig  = lane & 3;
    const int mrow  = (warp & 3) * 32;
    const int nbase = (warp >> 2) * 32;
    const int half  = lane >> 4;            // 0/1
    const int j     = lane & 15;            // 0..15

    const float4* P4 = (const float4*)g_P;
    const unsigned fsb = (unsigned)__cvta_generic_to_shared(fsmall);
    const unsigned msb = (unsigned)__cvta_generic_to_shared(msg);

    __syncthreads();   // weights + pad ready

    const int nTiles = (E + E_TILE - 1) / E_TILE;
    for (int t = blockIdx.x; t < nTiles; t += gridDim.x) {
        const int base = t * E_TILE;

        // ========== STAGE A: no writes to presum/msg/ds ==========
        const int eb = base + warp * 16;
        int egi = eb + j; if (egi >= E) egi = E - 1;
        const int myidx = (lane < 16) ? src[egi] : dst[egi];

        #pragma unroll
        for (int r = 0; r < 2; r++) {
            int el = warp * 16 + r * 8 + (lane >> 2);
            int eg = base + el; if (eg >= E) eg = E - 1;
            int c = lane & 3;
            cp16(fsb + el * (FSSTR * 4) + c * 16,
                 edge_feat + (long)eg * 16 + c * 4);
        }
        asm volatile("cp.async.commit_group;");

        // P gather: all 16 LDG.128 issued before any consume
        float4 ps[8], pd[8];
        #pragma unroll
        for (int i = 0; i < 8; i++) {
            int el = i * 2 + half;
            int s = __shfl_sync(0xffffffffu, myidx, el);
            int d = __shfl_sync(0xffffffffu, myidx, 16 + el);
            ps[i] = P4[(long)s * 32 + j];
            pd[i] = P4[(long)d * 32 + 16 + j];
        }

        // radial (lanes 0..15)
        int s_r = __shfl_sync(0xffffffffu, myidx, j);
        int d_r = __shfl_sync(0xffffffffu, myidx, 16 + j);
        if (lane < 16) {
            float cx = coord[s_r * 3 + 0] - coord[d_r * 3 + 0];
            float cy = coord[s_r * 3 + 1] - coord[d_r * 3 + 1];
            float cz = coord[s_r * 3 + 2] - coord[d_r * 3 + 2];
            fsmall[(warp * 16 + j) * FSSTR + 16]
                = cx * cx + cy * cy + cz * cz;
        }

        // ========== drain previous tile's bulk scatter ==========
        asm volatile("cp.async.bulk.wait_group 0;" ::: "memory");
        __syncthreads();

        // store presum + ds (msg region now safe to overwrite)
        #pragma unroll
        for (int i = 0; i < 8; i++) {
            int el = warp * 16 + i * 2 + half;
            float4 v = make_float4(ps[i].x + pd[i].x, ps[i].y + pd[i].y,
                                   ps[i].z + pd[i].z, ps[i].w + pd[i].w);
            *(float4*)(presum + el * PSTR + j * 4) = v;
        }
        if (lane >= 16) ds[warp * 16 + j] = d_r;

        asm volatile("cp.async.wait_group 0;");
        __syncthreads();

        // ========== GEMM1: [128,24]@[24,64] ==========
        float d1[2][4][4];
        #pragma unroll
        for (int mi = 0; mi < 2; mi++)
            #pragma unroll
            for (int nj = 0; nj < 4; nj++)
                #pragma unroll
                for (int q = 0; q < 4; q++) d1[mi][nj][q] = 0.0f;

        const unsigned* w1u = (const unsigned*)W1s;
        #pragma unroll
        for (int ks = 0; ks < 3; ks++) {
            const int kk = ks * 8;
            unsigned a[2][4];
            #pragma unroll
            for (int mi = 0; mi < 2; mi++) {
                int r0 = mrow + mi * 16 + gid;
                const float* fp  = fsmall + r0 * FSSTR + kk + tig;
                const float* fp8 = fp + 8 * FSSTR;
                a[mi][0] = f2tf(fp[0]);
                a[mi][1] = f2tf(fp8[0]);
                a[mi][2] = f2tf(fp[4]);
                a[mi][3] = f2tf(fp8[4]);
            }
            #pragma unroll
            for (int nj = 0; nj < 4; nj++) {
                int n = nbase + nj * 8 + gid;
                unsigned bb[2];
                bb[0] = w1u[(kk + tig) * WSTR + n];
                bb[1] = w1u[(kk + tig + 4) * WSTR + n];
                mma_tf32(d1[0][nj], a[0], bb);
                mma_tf32(d1[1][nj], a[1], bb);
            }
        }

        // ---- epilogue1: m = tf32(silu(d1 + presum + b1)) ----
        #pragma unroll
        for (int mi = 0; mi < 2; mi++) {
            int r0 = mrow + mi * 16 + gid;
            #pragma unroll
            for (int nj = 0; nj < 4; nj++) {
                int c0 = nbase + nj * 8 + tig * 2;
                float bb0 = b1s[c0], bb1 = b1s[c0 + 1];
                m[r0 * MSTR + c0] = __uint_as_float(f2tf(
                    silu(d1[mi][nj][0] + presum[r0 * PSTR + c0] + bb0)));
                m[r0 * MSTR + c0 + 1] = __uint_as_float(f2tf(
                    silu(d1[mi][nj][1] + presum[r0 * PSTR + c0 + 1] + bb1)));
                m[(r0 + 8) * MSTR + c0] = __uint_as_float(f2tf(
                    silu(d1[mi][nj][2] + presum[(r0 + 8) * PSTR + c0] + bb0)));
                m[(r0 + 8) * MSTR + c0 + 1] = __uint_as_float(f2tf(
                    silu(d1[mi][nj][3] + presum[(r0 + 8) * PSTR + c0 + 1] + bb1)));
            }
        }
        __syncthreads();   // m complete; presum reads done

        // ========== GEMM2: [128,64]@[64,64] ==========
        float d2[2][4][4];
        #pragma unroll
        for (int mi = 0; mi < 2; mi++)
            #pragma unroll
            for (int nj = 0; nj < 4; nj++)
                #pragma unroll
                for (int q = 0; q < 4; q++) d2[mi][nj][q] = 0.0f;

        const unsigned* msu = (const unsigned*)m;
        const unsigned* w2u = (const unsigned*)W2s;
        #pragma unroll
        for (int ks = 0; ks < 8; ks++) {
            const int kk = ks * 8;
            unsigned a[2][4];
            #pragma unroll
            for (int mi = 0; mi < 2; mi++) {
                int r0 = mrow + mi * 16 + gid;
                const unsigned* mp  = msu + r0 * MSTR + kk + tig;
                const unsigned* mp8 = mp + 8 * MSTR;
                a[mi][0] = mp[0];
                a[mi][1] = mp8[0];
                a[mi][2] = mp[4];
                a[mi][3] = mp8[4];
            }
            #pragma unroll
            for (int nj = 0; nj < 4; nj++) {
                int n = nbase + nj * 8 + gid;
                unsigned bb[2];
                bb[0] = w2u[(kk + tig) * WSTR + n];
                bb[1] = w2u[(kk + tig + 4) * WSTR + n];
                mma_tf32(d2[0][nj], a[0], bb);
                mma_tf32(d2[1][nj], a[1], bb);
            }
        }

        // ---- epilogue2: msg = silu(d2 + b2) ----
        #pragma unroll
        for (int mi = 0; mi < 2; mi++) {
            int r0 = mrow + mi * 16 + gid;
            #pragma unroll
            for (int nj = 0; nj < 4; nj++) {
                int c0 = nbase + nj * 8 + tig * 2;
                float bb0 = b2s[c0], bb1 = b2s[c0 + 1];
                msg[r0 * PSTR + c0]           = silu(d2[mi][nj][0] + bb0);
                msg[r0 * PSTR + c0 + 1]       = silu(d2[mi][nj][1] + bb1);
                msg[(r0 + 8) * PSTR + c0]     = silu(d2[mi][nj][2] + bb0);
                msg[(r0 + 8) * PSTR + c0 + 1] = silu(d2[mi][nj][3] + bb1);
            }
        }
        __syncthreads();   // msg visible to all; ds ready

        // ========== scatter: bulk add-reduce, one edge per thread ==========
        asm volatile("fence.proxy.async.shared::cta;" ::: "memory");
        if (tid < E_TILE && base + tid < E) {
            bulk_red_add(g_hneigh + (long)ds[tid] * HH,
                         msb + tid * (PSTR * 4), HH * 4);
        }
        asm volatile("cp.async.bulk.commit_group;" ::: "memory");
    }
    // drain outstanding bulk ops before exit
    asm volatile("cp.async.bulk.wait_group 0;" ::: "memory");
}

// ---------------------------------------------------------------------------
// Node kernel: tf32 mma. z=[node_feat|h_neigh] (K=128).
// ---------------------------------------------------------------------------
#define N_TILE 256
#define ZSTR   132
#define THREADS 512

__global__ void __launch_bounds__(THREADS, 1)
node_kernel(const float* __restrict__ node_feat,
            const float* __restrict__ Wn1,
            const float* __restrict__ bn1,
            const float* __restrict__ Wn2,
            const float* __restrict__ bn2,
            float* __restrict__ out,
            int N)
{
    extern __shared__ float sm[];
    float* zs  = sm;                        // 256*132 (m aliases, stride 68)
    float* W1s = zs + N_TILE * ZSTR;        // 128*72
    float* W2s = W1s + 128 * WSTR;          // 64*72
    float* b1s = W2s + HH * WSTR;
    float* b2s = b1s + HH;

    const int tid = threadIdx.x;

    for (int i = tid; i < 128 * HH; i += THREADS) {
        int r = i / HH, c = i % HH;
        W1s[r * WSTR + c] = __uint_as_float(f2tf(Wn1[i]));
    }
    for (int i = tid; i < HH * DD; i += THREADS) {
        int r = i / DD, c = i % DD;
        W2s[r * WSTR + c] = __uint_as_float(f2tf(Wn2[i]));
    }
    if (tid < HH) { b1s[tid] = bn1[tid]; b2s[tid] = bn2[tid]; }

    const int warp = tid >> 5;
    const int lane = tid & 31;
    const int gid  = lane >> 2;
    const int tig  = lane & 3;
    const int mrow  = (warp & 7) * 32;
    const int nbase = (warp >> 3) * 32;

    const float4* nf4 = (const float4*)node_feat;
    const float4* hn4 = (const float4*)g_hneigh;

    const int nTiles = (N + N_TILE - 1) / N_TILE;
    for (int t = blockIdx.x; t < nTiles; t += gridDim.x) {
        const int base = t * N_TILE;
        __syncthreads();

        for (int idx = tid; idx < N_TILE * 32; idx += THREADS) {
            int nl = idx >> 5, c = idx & 31;
            int n = base + nl;
            if (n >= N) n = N - 1;
            float4 v = (c < 16) ? nf4[(long)n * 16 + c]
                                : hn4[(long)n * 16 + (c - 16)];
            ((float4*)(zs + nl * ZSTR))[c] = v;
        }
        __syncthreads();

        float d1[2][4][4];
        #pragma unroll
        for (int mi = 0; mi < 2; mi++)
            #pragma unroll
            for (int nj = 0; nj < 4; nj++)
                #pragma unroll
                for (int q = 0; q < 4; q++) d1[mi][nj][q] = 0.0f;

        const unsigned* w1u = (const unsigned*)W1s;
        #pragma unroll 4
        for (int ks = 0; ks < 16; ks++) {
            const int kk = ks * 8;
            unsigned a[2][4];
            #pragma unroll
            for (int mi = 0; mi < 2; mi++) {
                int r0 = mrow + mi * 16 + gid;
                const float* fp  = zs + r0 * ZSTR + kk + tig;
                const float* fp8 = fp + 8 * ZSTR;
                a[mi][0] = f2tf(fp[0]);
                a[mi][1] = f2tf(fp8[0]);
                a[mi][2] = f2tf(fp[4]);
                a[mi][3] = f2tf(fp8[4]);
            }
            #pragma unroll
            for (int nj = 0; nj < 4; nj++) {
                int n = nbase + nj * 8 + gid;
                unsigned bb[2];
                bb[0] = w1u[(kk + tig) * WSTR + n];
                bb[1] = w1u[(kk + tig + 4) * WSTR + n];
                mma_tf32(d1[0][nj], a[0], bb);
                mma_tf32(d1[1][nj], a[1], bb);
            }
        }
        __syncthreads();

        #pragma unroll
        for (int mi = 0; mi < 2; mi++) {
            int r0 = mrow + mi * 16 + gid;
            #pragma unroll
            for (int nj = 0; nj < 4; nj++) {
                int c0 = nbase + nj * 8 + tig * 2;
                float bb0 = b1s[c0], bb1 = b1s[c0 + 1];
                zs[r0 * MSTR + c0]
                    = __uint_as_float(f2tf(silu(d1[mi][nj][0] + bb0)));
                zs[r0 * MSTR + c0 + 1]
                    = __uint_as_float(f2tf(silu(d1[mi][nj][1] + bb1)));
                zs[(r0 + 8) * MSTR + c0]
                    = __uint_as_float(f2tf(silu(d1[mi][nj][2] + bb0)));
                zs[(r0 + 8) * MSTR + c0 + 1]
                    = __uint_as_float(f2tf(silu(d1[mi][nj][3] + bb1)));
            }
        }
        __syncthreads();

        float d2[2][4][4];
        #pragma unroll
        for (int mi = 0; mi < 2; mi++)
            #pragma unroll
            for (int nj = 0; nj < 4; nj++)
                #pragma unroll
                for (int q = 0; q < 4; q++) d2[mi][nj][q] = 0.0f;

        const unsigned* msu = (const unsigned*)zs;
        const unsigned* w2u = (const unsigned*)W2s;
        #pragma unroll
        for (int ks = 0; ks < 8; ks++) {
            const int kk = ks * 8;
            unsigned a[2][4];
            #pragma unroll
            for (int mi = 0; mi < 2; mi++) {
                int r0 = mrow + mi * 16 + gid;
                const unsigned* mp  = msu + r0 * MSTR + kk + tig;
                const unsigned* mp8 = mp + 8 * MSTR;
                a[mi][0] = mp[0];
                a[mi][1] = mp8[0];
                a[mi][2] = mp[4];
                a[mi][3] = mp8[4];
            }
            #pragma unroll
            for (int nj = 0; nj < 4; nj++) {
                int n = nbase + nj * 8 + gid;
                unsigned bb[2];
                bb[0] = w2u[(kk + tig) * WSTR + n];
                bb[1] = w2u[(kk + tig + 4) * WSTR + n];
                mma_tf32(d2[0][nj], a[0], bb);
                mma_tf32(d2[1][nj], a[1], bb);
            }
        }

        #pragma unroll
        for (int mi = 0; mi < 2; mi++) {
            int r0 = mrow + mi * 16 + gid;
            #pragma unroll
            for (int nj = 0; nj < 4; nj++) {
                int c0 = nbase + nj * 8 + tig * 2;
                float bb0 = b2s[c0], bb1 = b2s[c0 + 1];
                int n0 = base + r0, n1 = base + r0 + 8;
                if (n0 < N)
                    *(float2*)(out + (long)n0 * DD + c0)
                        = make_float2(d2[mi][nj][0] + bb0, d2[mi][nj][1] + bb1);
                if (n1 < N)
                    *(float2*)(out + (long)n1 * DD + c0)
                        = make_float2(d2[mi][nj][2] + bb0, d2[mi][nj][3] + bb1);
            }
        }
    }
}

// ---------------------------------------------------------------------------
extern "C" void kernel_launch(void* const* d_in, const int* in_sizes, int n_in,
                              void* d_out, int out_size)
{
    const float* node_feat = (const float*)d_in[0];
    const float* coord     = (const float*)d_in[1];
    const float* edge_feat = (const float*)d_in[2];
    const int*   src       = (const int*)d_in[3];
    const int*   dst       = (const int*)d_in[4];
    const float* We1       = (const float*)d_in[5];
    const float* be1       = (const float*)d_in[6];
    const float* We2       = (const float*)d_in[7];
    const float* be2       = (const float*)d_in[8];
    const float* Wn1       = (const float*)d_in[9];
    const float* bn1       = (const float*)d_in[10];
    const float* Wn2       = (const float*)d_in[11];
    const float* bn2       = (const float*)d_in[12];
    float* out = (float*)d_out;

    const int N = in_sizes[0] / DD;
    const int E = in_sizes[3];

    const size_t smem_p =
        (size_t)(128 * ASTR + 64 * BSTR2) * sizeof(float);
    const size_t smem_edge =
        (size_t)(K1S * WSTR + HH * WSTR + 2 * HH + E_TILE
                 + E_TILE * PSTR + E_TILE * FSSTR + E_TILE * MSTR)
        * sizeof(float);   // 110336
    const size_t smem_node =
        (size_t)(N_TILE * ZSTR + 128 * WSTR + HH * WSTR + 2 * HH)
        * sizeof(float);

    cudaFuncSetAttribute(p_kernel,
                         cudaFuncAttributeMaxDynamicSharedMemorySize,
                         (int)smem_p);
    cudaFuncSetAttribute(edge_kernel,
                         cudaFuncAttributeMaxDynamicSharedMemorySize,
                         (int)smem_edge);
    cudaFuncSetAttribute(node_kernel,
                         cudaFuncAttributeMaxDynamicSharedMemorySize,
                         (int)smem_node);

    int numSMs = 148;
    cudaDeviceGetAttribute(&numSMs, cudaDevAttrMultiProcessorCount, 0);

    // 1) P precompute + zero g_hneigh (fused grid)
    int pTiles = (N + 127) / 128;
    p_kernel<<<pTiles + 120, 512, smem_p>>>(node_feat, We1, N, pTiles);

    // 2) edge MLP + bulk-reduce scatter (persistent, 2 CTAs/SM)
    int eTiles = (E + E_TILE - 1) / E_TILE;
    int eGrid = 2 * numSMs;
    if (eGrid > eTiles) eGrid = eTiles;
    edge_kernel<<<eGrid, ETHREADS, smem_edge>>>(
        coord, edge_feat, src, dst, We1, be1, We2, be2, E);

    // 3) node MLP
    int nTiles = (N + N_TILE - 1) / N_TILE;
    int nGrid = nTiles < numSMs ? nTiles : numSMs;
    node_kernel<<<nGrid, THREADS, smem_node>>>(
        node_feat, Wn1, bn1, Wn2, bn2, out, N);
}

// round 7
// speedup vs baseline: 7.0123x; 1.1600x over previous
#include <cuda_runtime.h>

// ---------------------------------------------------------------------------
// EGNN edge/node block, round 7.
// P[n] = [h_n@W1_src | h_n@W1_dst] precomputed (+fused zero of g_hneigh).
// Edge kernel: single shared buffer for presum/m/msg (in-place epilogues)
// -> 75.5 KB smem -> 3 CTAs/SM (occupancy was the binding constraint).
// tf32 mma.sync GEMMs, bulk-async add-reduce scatter.
// N=50000, E=800000, D=64, H=64, EF=16.
// ---------------------------------------------------------------------------

#define NN      50000
#define DD      64
#define HH      64
#define E_TILE  128
#define WSTR    72     // weight row stride (72%32=8, conflict-free)
#define PSTR    68     // buf row stride (68%32=4); 272B row, 16B-aligned
#define FSSTR   28     // fsmall row stride (28%32=28, conflict-free)
#define K1S     24     // padded small-K of edge layer 1 (3 k-steps)

__device__ float g_hneigh[NN * HH];
__device__ float g_P[NN * 128];   // [n][0:64]=h@W1_src, [64:128]=h@W1_dst

__device__ __forceinline__ float silu(float x) {
    return x / (1.0f + __expf(-x));
}
__device__ __forceinline__ unsigned f2tf(float x) {
    unsigned r;
    asm("cvt.rna.tf32.f32 %0, %1;" : "=r"(r) : "f"(x));
    return r;
}
__device__ __forceinline__ void mma_tf32(float d[4], const unsigned a[4],
                                         const unsigned b[2]) {
    asm volatile(
        "mma.sync.aligned.m16n8k8.row.col.f32.tf32.tf32.f32 "
        "{%0,%1,%2,%3}, {%4,%5,%6,%7}, {%8,%9}, {%0,%1,%2,%3};"
        : "+f"(d[0]), "+f"(d[1]), "+f"(d[2]), "+f"(d[3])
        : "r"(a[0]), "r"(a[1]), "r"(a[2]), "r"(a[3]), "r"(b[0]), "r"(b[1]));
}
__device__ __forceinline__ void cp16(unsigned saddr, const void* g) {
    asm volatile("cp.async.ca.shared.global [%0], [%1], 16;"
                 :: "r"(saddr), "l"(g));
}
__device__ __forceinline__ void bulk_red_add(float* gptr, unsigned saddr,
                                             int bytes) {
    unsigned long long g;
    asm("cvta.to.global.u64 %0, %1;" : "=l"(g) : "l"(gptr));
    asm volatile(
        "cp.reduce.async.bulk.global.shared::cta.bulk_group.add.f32 "
        "[%0], [%1], %2;"
        :: "l"(g), "r"(saddr), "r"(bytes) : "memory");
}

// ---------------------------------------------------------------------------
// P kernel (+ fused zeroing of g_hneigh by trailing blocks).
// ---------------------------------------------------------------------------
#define ASTR  68
#define BSTR2 136

__global__ void __launch_bounds__(512, 1)
p_kernel(const float* __restrict__ node_feat,
         const float* __restrict__ We1,
         int N, int pTiles)
{
    const int tid = threadIdx.x;

    if ((int)blockIdx.x >= pTiles) {
        const int zb = blockIdx.x - pTiles;
        float4* h4 = (float4*)g_hneigh;
        const int total4 = NN * HH / 4;
        for (int i = zb * 512 + tid; i < total4; i += (gridDim.x - pTiles) * 512)
            h4[i] = make_float4(0.f, 0.f, 0.f, 0.f);
        return;
    }

    extern __shared__ float sm[];
    float* As = sm;                 // 128*68
    float* Bs = As + 128 * ASTR;    // 64*136

    for (int i = tid; i < 64 * 128; i += 512) {
        int k = i >> 7, j = i & 127;
        float v = (j < 64) ? We1[k * HH + j] : We1[(64 + k) * HH + (j - 64)];
        Bs[k * BSTR2 + j] = __uint_as_float(f2tf(v));
    }
    const int base = blockIdx.x * 128;
    const float4* nf4 = (const float4*)node_feat;
    for (int idx = tid; idx < 128 * 16; idx += 512) {
        int r = idx >> 4, c = idx & 15;
        int n = base + r;
        if (n >= N) n = N - 1;
        ((float4*)(As + r * ASTR))[c] = nf4[(long)n * 16 + c];
    }
    __syncthreads();

    const int warp = tid >> 5, lane = tid & 31;
    const int gid = lane >> 2, tig = lane & 3;
    const int mrow  = (warp & 3) * 32;
    const int nbase = (warp >> 2) * 32;

    float d[2][4][4];
    #pragma unroll
    for (int mi = 0; mi < 2; mi++)
        #pragma unroll
        for (int nj = 0; nj < 4; nj++)
            #pragma unroll
            for (int q = 0; q < 4; q++) d[mi][nj][q] = 0.0f;

    const unsigned* bu = (const unsigned*)Bs;
    #pragma unroll
    for (int ks = 0; ks < 8; ks++) {
        const int kk = ks * 8;
        unsigned a[2][4];
        #pragma unroll
        for (int mi = 0; mi < 2; mi++) {
            int r0 = mrow + mi * 16 + gid;
            const float* fp  = As + r0 * ASTR + kk + tig;
            const float* fp8 = fp + 8 * ASTR;
            a[mi][0] = f2tf(fp[0]);
            a[mi][1] = f2tf(fp8[0]);
            a[mi][2] = f2tf(fp[4]);
            a[mi][3] = f2tf(fp8[4]);
        }
        #pragma unroll
        for (int nj = 0; nj < 4; nj++) {
            int n = nbase + nj * 8 + gid;
            unsigned bb[2];
            bb[0] = bu[(kk + tig) * BSTR2 + n];
            bb[1] = bu[(kk + tig + 4) * BSTR2 + n];
            mma_tf32(d[0][nj], a[0], bb);
            mma_tf32(d[1][nj], a[1], bb);
        }
    }
    #pragma unroll
    for (int mi = 0; mi < 2; mi++) {
        int r0 = mrow + mi * 16 + gid;
        #pragma unroll
        for (int nj = 0; nj < 4; nj++) {
            int c0 = nbase + nj * 8 + tig * 2;
            int n0 = base + r0, n1 = base + r0 + 8;
            if (n0 < N)
                *(float2*)(g_P + (long)n0 * 128 + c0)
                    = make_float2(d[mi][nj][0], d[mi][nj][1]);
            if (n1 < N)
                *(float2*)(g_P + (long)n1 * 128 + c0)
                    = make_float2(d[mi][nj][2], d[mi][nj][3]);
        }
    }
}

// ---------------------------------------------------------------------------
// Edge kernel. Single buf region: presum -> m (in-place) -> msg (in-place).
// Per tile: stage A (indices, cp.async edge_feat, radial), bulk.wait+sync,
// presum store, sync, GEMM1+epi1(in-place), sync, GEMM2, sync,
// epi2(in-place), sync, bulk scatter issue.
// 256 threads, 3 CTAs/SM.
// ---------------------------------------------------------------------------
#define ETHREADS 256

__global__ void __launch_bounds__(ETHREADS, 3)
edge_kernel(const float* __restrict__ coord,
            const float* __restrict__ edge_feat,
            const int*   __restrict__ src,
            const int*   __restrict__ dst,
            const float* __restrict__ We1,
            const float* __restrict__ be1,
            const float* __restrict__ We2,
            const float* __restrict__ be2,
            int E)
{
    extern __shared__ float sm[];
    float* W1s    = sm;                      // 24*72   = 1728
    float* W2s    = W1s + K1S * WSTR;        // 64*72   = 4608
    float* b1s    = W2s + HH * WSTR;         // 64
    float* b2s    = b1s + HH;                // 64
    int*   ds     = (int*)(b2s + HH);        // 128
    float* buf    = (float*)(ds + E_TILE);   // 128*68 = 8704 (presum/m/msg)
    float* fsmall = buf + E_TILE * PSTR;     // 128*28 = 3584
    // total 18880 floats = 75520 B -> 3 CTAs/SM

    const int tid = threadIdx.x;

    for (int i = tid; i < K1S * HH; i += ETHREADS) {
        int r = i / HH, c = i % HH;
        float v = 0.0f;
        if (r < 16)       v = We1[(129 + r) * HH + c];
        else if (r == 16) v = We1[128 * HH + c];
        W1s[r * WSTR + c] = __uint_as_float(f2tf(v));
    }
    for (int i = tid; i < HH * HH; i += ETHREADS) {
        int r = i / HH, c = i % HH;
        W2s[r * WSTR + c] = __uint_as_float(f2tf(We2[i]));
    }
    if (tid < HH) { b1s[tid] = be1[tid]; b2s[tid] = be2[tid]; }
    for (int i = tid; i < E_TILE * 11; i += ETHREADS) {
        int r = i / 11, c = 17 + (i % 11);
        fsmall[r * FSSTR + c] = 0.0f;        // constant K-pad, written once
    }

    const int warp = tid >> 5;
    const int lane = tid & 31;
    const int gid  = lane >> 2;
    const int tig  = lane & 3;
    const int mrow  = (warp & 3) * 32;
    const int nbase = (warp >> 2) * 32;
    const int half  = lane >> 4;            // 0/1
    const int j     = lane & 15;            // 0..15

    const float4* P4 = (const float4*)g_P;
    const unsigned fsb = (unsigned)__cvta_generic_to_shared(fsmall);
    const unsigned msb = (unsigned)__cvta_generic_to_shared(buf);

    __syncthreads();   // weights + pad ready

    const int nTiles = (E + E_TILE - 1) / E_TILE;
    for (int t = blockIdx.x; t < nTiles; t += gridDim.x) {
        const int base = t * E_TILE;

        // ========== STAGE A: no writes to buf/ds ==========
        const int eb = base + warp * 16;
        int egi = eb + j; if (egi >= E) egi = E - 1;
        const int myidx = (lane < 16) ? src[egi] : dst[egi];

        #pragma unroll
        for (int r = 0; r < 2; r++) {
            int el = warp * 16 + r * 8 + (lane >> 2);
            int eg = base + el; if (eg >= E) eg = E - 1;
            int c = lane & 3;
            cp16(fsb + el * (FSSTR * 4) + c * 16,
                 edge_feat + (long)eg * 16 + c * 4);
        }
        asm volatile("cp.async.commit_group;");

        // radial (lanes 0..15) + dst idx kept in reg
        int s_r = __shfl_sync(0xffffffffu, myidx, j);
        int d_r = __shfl_sync(0xffffffffu, myidx, 16 + j);
        if (lane < 16) {
            float cx = coord[s_r * 3 + 0] - coord[d_r * 3 + 0];
            float cy = coord[s_r * 3 + 1] - coord[d_r * 3 + 1];
            float cz = coord[s_r * 3 + 2] - coord[d_r * 3 + 2];
            fsmall[(warp * 16 + j) * FSSTR + 16]
                = cx * cx + cy * cy + cz * cz;
        }

        // ========== drain previous tile's bulk scatter ==========
        asm volatile("cp.async.bulk.wait_group 0;" ::: "memory");
        __syncthreads();

        // P gather + presum store, 2 chunks of 4 edges (reg-pressure cap)
        #pragma unroll
        for (int ch = 0; ch < 2; ch++) {
            float4 ps[4], pd[4];
            #pragma unroll
            for (int i = 0; i < 4; i++) {
                int el = (ch * 4 + i) * 2 + half;
                int s = __shfl_sync(0xffffffffu, myidx, el);
                int d = __shfl_sync(0xffffffffu, myidx, 16 + el);
                ps[i] = P4[(long)s * 32 + j];
                pd[i] = P4[(long)d * 32 + 16 + j];
            }
            #pragma unroll
            for (int i = 0; i < 4; i++) {
                int el = warp * 16 + (ch * 4 + i) * 2 + half;
                float4 v = make_float4(ps[i].x + pd[i].x, ps[i].y + pd[i].y,
                                       ps[i].z + pd[i].z, ps[i].w + pd[i].w);
                *(float4*)(buf + el * PSTR + j * 4) = v;
            }
        }
        if (lane >= 16) ds[warp * 16 + j] = d_r;

        asm volatile("cp.async.wait_group 0;");
        __syncthreads();

        // ========== GEMM1: [128,24]@[24,64] ==========
        float d1[2][4][4];
        #pragma unroll
        for (int mi = 0; mi < 2; mi++)
            #pragma unroll
            for (int nj = 0; nj < 4; nj++)
                #pragma unroll
                for (int q = 0; q < 4; q++) d1[mi][nj][q] = 0.0f;

        const unsigned* w1u = (const unsigned*)W1s;
        #pragma unroll
        for (int ks = 0; ks < 3; ks++) {
            const int kk = ks * 8;
            unsigned a[2][4];
            #pragma unroll
            for (int mi = 0; mi < 2; mi++) {
                int r0 = mrow + mi * 16 + gid;
                const float* fp  = fsmall + r0 * FSSTR + kk + tig;
                const float* fp8 = fp + 8 * FSSTR;
                a[mi][0] = f2tf(fp[0]);
                a[mi][1] = f2tf(fp8[0]);
                a[mi][2] = f2tf(fp[4]);
                a[mi][3] = f2tf(fp8[4]);
            }
            #pragma unroll
            for (int nj = 0; nj < 4; nj++) {
                int n = nbase + nj * 8 + gid;
                unsigned bb[2];
                bb[0] = w1u[(kk + tig) * WSTR + n];
                bb[1] = w1u[(kk + tig + 4) * WSTR + n];
                mma_tf32(d1[0][nj], a[0], bb);
                mma_tf32(d1[1][nj], a[1], bb);
            }
        }

        // ---- epilogue1 IN-PLACE: buf[x] = tf32(silu(d1 + buf[x] + b1))
        //      (each element read+written by its owning thread only) ----
        #pragma unroll
        for (int mi = 0; mi < 2; mi++) {
            int r0 = mrow + mi * 16 + gid;
            #pragma unroll
            for (int nj = 0; nj < 4; nj++) {
                int c0 = nbase + nj * 8 + tig * 2;
                float bb0 = b1s[c0], bb1 = b1s[c0 + 1];
                float* p00 = buf + r0 * PSTR + c0;
                float* p10 = buf + (r0 + 8) * PSTR + c0;
                p00[0] = __uint_as_float(f2tf(silu(d1[mi][nj][0] + p00[0] + bb0)));
                p00[1] = __uint_as_float(f2tf(silu(d1[mi][nj][1] + p00[1] + bb1)));
                p10[0] = __uint_as_float(f2tf(silu(d1[mi][nj][2] + p10[0] + bb0)));
                p10[1] = __uint_as_float(f2tf(silu(d1[mi][nj][3] + p10[1] + bb1)));
            }
        }
        __syncthreads();   // m (in buf) complete

        // ========== GEMM2: [128,64]@[64,64] ==========
        float d2[2][4][4];
        #pragma unroll
        for (int mi = 0; mi < 2; mi++)
            #pragma unroll
            for (int nj = 0; nj < 4; nj++)
                #pragma unroll
                for (int q = 0; q < 4; q++) d2[mi][nj][q] = 0.0f;

        const unsigned* msu = (const unsigned*)buf;
        const unsigned* w2u = (const unsigned*)W2s;
        #pragma unroll
        for (int ks = 0; ks < 8; ks++) {
            const int kk = ks * 8;
            unsigned a[2][4];
            #pragma unroll
            for (int mi = 0; mi < 2; mi++) {
                int r0 = mrow + mi * 16 + gid;
                const unsigned* mp  = msu + r0 * PSTR + kk + tig;
                const unsigned* mp8 = mp + 8 * PSTR;
                a[mi][0] = mp[0];
                a[mi][1] = mp8[0];
                a[mi][2] = mp[4];
                a[mi][3] = mp8[4];
            }
            #pragma unroll
            for (int nj = 0; nj < 4; nj++) {
                int n = nbase + nj * 8 + gid;
                unsigned bb[2];
                bb[0] = w2u[(kk + tig) * WSTR + n];
                bb[1] = w2u[(kk + tig + 4) * WSTR + n];
                mma_tf32(d2[0][nj], a[0], bb);
                mma_tf32(d2[1][nj], a[1], bb);
            }
        }
        __syncthreads();   // all m reads done before msg overwrite

        // ---- epilogue2 IN-PLACE: buf[x] = silu(d2 + b2) ----
        #pragma unroll
        for (int mi = 0; mi < 2; mi++) {
            int r0 = mrow + mi * 16 + gid;
            #pragma unroll
            for (int nj = 0; nj < 4; nj++) {
                int c0 = nbase + nj * 8 + tig * 2;
                float bb0 = b2s[c0], bb1 = b2s[c0 + 1];
                float* p00 = buf + r0 * PSTR + c0;
                float* p10 = buf + (r0 + 8) * PSTR + c0;
                p00[0] = silu(d2[mi][nj][0] + bb0);
                p00[1] = silu(d2[mi][nj][1] + bb1);
                p10[0] = silu(d2[mi][nj][2] + bb0);
                p10[1] = silu(d2[mi][nj][3] + bb1);
            }
        }
        __syncthreads();   // msg visible; ds ready

        // ========== scatter: bulk add-reduce, one edge per thread ==========
        asm volatile("fence.proxy.async.shared::cta;" ::: "memory");
        if (tid < E_TILE && base + tid < E) {
            bulk_red_add(g_hneigh + (long)ds[tid] * HH,
                         msb + tid * (PSTR * 4), HH * 4);
        }
        asm volatile("cp.async.bulk.commit_group;" ::: "memory");
    }
    asm volatile("cp.async.bulk.wait_group 0;" ::: "memory");
}

// ---------------------------------------------------------------------------
// Node kernel: tf32 mma. z=[node_feat|h_neigh] (K=128).
// ---------------------------------------------------------------------------
#define N_TILE 256
#define ZSTR   132
#define MSTR   68
#define THREADS 512

__global__ void __launch_bounds__(THREADS, 1)
node_kernel(const float* __restrict__ node_feat,
            const float* __restrict__ Wn1,
            const float* __restrict__ bn1,
            const float* __restrict__ Wn2,
            const float* __restrict__ bn2,
            float* __restrict__ out,
            int N)
{
    extern __shared__ float sm[];
    float* zs  = sm;                        // 256*132 (m aliases, stride 68)
    float* W1s = zs + N_TILE * ZSTR;        // 128*72
    float* W2s = W1s + 128 * WSTR;          // 64*72
    float* b1s = W2s + HH * WSTR;
    float* b2s = b1s + HH;

    const int tid = threadIdx.x;

    for (int i = tid; i < 128 * HH; i += THREADS) {
        int r = i / HH, c = i % HH;
        W1s[r * WSTR + c] = __uint_as_float(f2tf(Wn1[i]));
    }
    for (int i = tid; i < HH * DD; i += THREADS) {
        int r = i / DD, c = i % DD;
        W2s[r * WSTR + c] = __uint_as_float(f2tf(Wn2[i]));
    }
    if (tid < HH) { b1s[tid] = bn1[tid]; b2s[tid] = bn2[tid]; }

    const int warp = tid >> 5;
    const int lane = tid & 31;
    const int gid  = lane >> 2;
    const int tig  = lane & 3;
    const int mrow  = (warp & 7) * 32;
    const int nbase = (warp >> 3) * 32;

    const float4* nf4 = (const float4*)node_feat;
    const float4* hn4 = (const float4*)g_hneigh;

    const int nTiles = (N + N_TILE - 1) / N_TILE;
    for (int t = blockIdx.x; t < nTiles; t += gridDim.x) {
        const int base = t * N_TILE;
        __syncthreads();

        for (int idx = tid; idx < N_TILE * 32; idx += THREADS) {
            int nl = idx >> 5, c = idx & 31;
            int n = base + nl;
            if (n >= N) n = N - 1;
            float4 v = (c < 16) ? nf4[(long)n * 16 + c]
                                : hn4[(long)n * 16 + (c - 16)];
            ((float4*)(zs + nl * ZSTR))[c] = v;
        }
        __syncthreads();

        float d1[2][4][4];
        #pragma unroll
        for (int mi = 0; mi < 2; mi++)
            #pragma unroll
            for (int nj = 0; nj < 4; nj++)
                #pragma unroll
                for (int q = 0; q < 4; q++) d1[mi][nj][q] = 0.0f;

        const unsigned* w1u = (const unsigned*)W1s;
        #pragma unroll 4
        for (int ks = 0; ks < 16; ks++) {
            const int kk = ks * 8;
            unsigned a[2][4];
            #pragma unroll
            for (int mi = 0; mi < 2; mi++) {
                int r0 = mrow + mi * 16 + gid;
                const float* fp  = zs + r0 * ZSTR + kk + tig;
                const float* fp8 = fp + 8 * ZSTR;
                a[mi][0] = f2tf(fp[0]);
                a[mi][1] = f2tf(fp8[0]);
                a[mi][2] = f2tf(fp[4]);
                a[mi][3] = f2tf(fp8[4]);
            }
            #pragma unroll
            for (int nj = 0; nj < 4; nj++) {
                int n = nbase + nj * 8 + gid;
                unsigned bb[2];
                bb[0] = w1u[(kk + tig) * WSTR + n];
                bb[1] = w1u[(kk + tig + 4) * WSTR + n];
                mma_tf32(d1[0][nj], a[0], bb);
                mma_tf32(d1[1][nj], a[1], bb);
            }
        }
        __syncthreads();

        #pragma unroll
        for (int mi = 0; mi < 2; mi++) {
            int r0 = mrow + mi * 16 + gid;
            #pragma unroll
            for (int nj = 0; nj < 4; nj++) {
                int c0 = nbase + nj * 8 + tig * 2;
                float bb0 = b1s[c0], bb1 = b1s[c0 + 1];
                zs[r0 * MSTR + c0]
                    = __uint_as_float(f2tf(silu(d1[mi][nj][0] + bb0)));
                zs[r0 * MSTR + c0 + 1]
                    = __uint_as_float(f2tf(silu(d1[mi][nj][1] + bb1)));
                zs[(r0 + 8) * MSTR + c0]
                    = __uint_as_float(f2tf(silu(d1[mi][nj][2] + bb0)));
                zs[(r0 + 8) * MSTR + c0 + 1]
                    = __uint_as_float(f2tf(silu(d1[mi][nj][3] + bb1)));
            }
        }
        __syncthreads();

        float d2[2][4][4];
        #pragma unroll
        for (int mi = 0; mi < 2; mi++)
            #pragma unroll
            for (int nj = 0; nj < 4; nj++)
                #pragma unroll
                for (int q = 0; q < 4; q++) d2[mi][nj][q] = 0.0f;

        const unsigned* msu = (const unsigned*)zs;
        const unsigned* w2u = (const unsigned*)W2s;
        #pragma unroll
        for (int ks = 0; ks < 8; ks++) {
            const int kk = ks * 8;
            unsigned a[2][4];
            #pragma unroll
            for (int mi = 0; mi < 2; mi++) {
                int r0 = mrow + mi * 16 + gid;
                const unsigned* mp  = msu + r0 * MSTR + kk + tig;
                const unsigned* mp8 = mp + 8 * MSTR;
                a[mi][0] = mp[0];
                a[mi][1] = mp8[0];
                a[mi][2] = mp[4];
                a[mi][3] = mp8[4];
            }
            #pragma unroll
            for (int nj = 0; nj < 4; nj++) {
                int n = nbase + nj * 8 + gid;
                unsigned bb[2];
                bb[0] = w2u[(kk + tig) * WSTR + n];
                bb[1] = w2u[(kk + tig + 4) * WSTR + n];
                mma_tf32(d2[0][nj], a[0], bb);
                mma_tf32(d2[1][nj], a[1], bb);
            }
        }

        #pragma unroll
        for (int mi = 0; mi < 2; mi++) {
            int r0 = mrow + mi * 16 + gid;
            #pragma unroll
            for (int nj = 0; nj < 4; nj++) {
                int c0 = nbase + nj * 8 + tig * 2;
                float bb0 = b2s[c0], bb1 = b2s[c0 + 1];
                int n0 = base + r0, n1 = base + r0 + 8;
                if (n0 < N)
                    *(float2*)(out + (long)n0 * DD + c0)
                        = make_float2(d2[mi][nj][0] + bb0, d2[mi][nj][1] + bb1);
                if (n1 < N)
                    *(float2*)(out + (long)n1 * DD + c0)
                        = make_float2(d2[mi][nj][2] + bb0, d2[mi][nj][3] + bb1);
            }
        }
    }
}

// ---------------------------------------------------------------------------
extern "C" void kernel_launch(void* const* d_in, const int* in_sizes, int n_in,
                              void* d_out, int out_size)
{
    const float* node_feat = (const float*)d_in[0];
    const float* coord     = (const float*)d_in[1];
    const float* edge_feat = (const float*)d_in[2];
    const int*   src       = (const int*)d_in[3];
    const int*   dst       = (const int*)d_in[4];
    const float* We1       = (const float*)d_in[5];
    const float* be1       = (const float*)d_in[6];
    const float* We2       = (const float*)d_in[7];
    const float* be2       = (const float*)d_in[8];
    const float* Wn1       = (const float*)d_in[9];
    const float* bn1       = (const float*)d_in[10];
    const float* Wn2       = (const float*)d_in[11];
    const float* bn2       = (const float*)d_in[12];
    float* out = (float*)d_out;

    const int N = in_sizes[0] / DD;
    const int E = in_sizes[3];

    const size_t smem_p =
        (size_t)(128 * ASTR + 64 * BSTR2) * sizeof(float);
    const size_t smem_edge =
        (size_t)(K1S * WSTR + HH * WSTR + 2 * HH + E_TILE
                 + E_TILE * PSTR + E_TILE * FSSTR)
        * sizeof(float);   // 75520 B -> 3 CTAs/SM
    const size_t smem_node =
        (size_t)(N_TILE * ZSTR + 128 * WSTR + HH * WSTR + 2 * HH)
        * sizeof(float);

    cudaFuncSetAttribute(p_kernel,
                         cudaFuncAttributeMaxDynamicSharedMemorySize,
                         (int)smem_p);
    cudaFuncSetAttribute(edge_kernel,
                         cudaFuncAttributeMaxDynamicSharedMemorySize,
                         (int)smem_edge);
    cudaFuncSetAttribute(node_kernel,
                         cudaFuncAttributeMaxDynamicSharedMemorySize,
                         (int)smem_node);

    int numSMs = 148;
    cudaDeviceGetAttribute(&numSMs, cudaDevAttrMultiProcessorCount, 0);

    // 1) P precompute + zero g_hneigh (fused grid)
    int pTiles = (N + 127) / 128;
    p_kernel<<<pTiles + 120, 512, smem_p>>>(node_feat, We1, N, pTiles);

    // 2) edge MLP + bulk-reduce scatter (persistent, 3 CTAs/SM)
    int eTiles = (E + E_TILE - 1) / E_TILE;
    int eGrid = 3 * numSMs;
    if (eGrid > eTiles) eGrid = eTiles;
    edge_kernel<<<eGrid, ETHREADS, smem_edge>>>(
        coord, edge_feat, src, dst, We1, be1, We2, be2, E);

    // 3) node MLP
    int nTiles = (N + N_TILE - 1) / N_TILE;
    int nGrid = nTiles < numSMs ? nTiles : numSMs;
    node_kernel<<<nGrid, THREADS, smem_node>>>(
        node_feat, Wn1, bn1, Wn2, bn2, out, N);
}

// round 8
// speedup vs baseline: 7.2004x; 1.0268x over previous
#include <cuda_runtime.h>

// ---------------------------------------------------------------------------
// EGNN edge/node block, round 8.
// R7 + occupancy fixes: p_kernel 2 CTAs/SM (reg cap), node_kernel 1024 thr
// (32 warps, m16 tiles), edge gather chunk-1 hoisted above bulk drain.
// N=50000, E=800000, D=64, H=64, EF=16.
// ---------------------------------------------------------------------------

#define NN      50000
#define DD      64
#define HH      64
#define E_TILE  128
#define WSTR    72     // weight row stride (72%32=8, conflict-free)
#define PSTR    68     // buf row stride (68%32=4); 272B row, 16B-aligned
#define FSSTR   28     // fsmall row stride (28%32=28, conflict-free)
#define K1S     24     // padded small-K of edge layer 1 (3 k-steps)

__device__ float g_hneigh[NN * HH];
__device__ float g_P[NN * 128];   // [n][0:64]=h@W1_src, [64:128]=h@W1_dst

__device__ __forceinline__ float silu(float x) {
    return x / (1.0f + __expf(-x));
}
__device__ __forceinline__ unsigned f2tf(float x) {
    unsigned r;
    asm("cvt.rna.tf32.f32 %0, %1;" : "=r"(r) : "f"(x));
    return r;
}
__device__ __forceinline__ void mma_tf32(float d[4], const unsigned a[4],
                                         const unsigned b[2]) {
    asm volatile(
        "mma.sync.aligned.m16n8k8.row.col.f32.tf32.tf32.f32 "
        "{%0,%1,%2,%3}, {%4,%5,%6,%7}, {%8,%9}, {%0,%1,%2,%3};"
        : "+f"(d[0]), "+f"(d[1]), "+f"(d[2]), "+f"(d[3])
        : "r"(a[0]), "r"(a[1]), "r"(a[2]), "r"(a[3]), "r"(b[0]), "r"(b[1]));
}
__device__ __forceinline__ void cp16(unsigned saddr, const void* g) {
    asm volatile("cp.async.ca.shared.global [%0], [%1], 16;"
                 :: "r"(saddr), "l"(g));
}
__device__ __forceinline__ void bulk_red_add(float* gptr, unsigned saddr,
                                             int bytes) {
    unsigned long long g;
    asm("cvta.to.global.u64 %0, %1;" : "=l"(g) : "l"(gptr));
    asm volatile(
        "cp.reduce.async.bulk.global.shared::cta.bulk_group.add.f32 "
        "[%0], [%1], %2;"
        :: "l"(g), "r"(saddr), "r"(bytes) : "memory");
}

// ---------------------------------------------------------------------------
// P kernel (+ fused zeroing of g_hneigh by trailing blocks). 2 CTAs/SM.
// ---------------------------------------------------------------------------
#define ASTR  68
#define BSTR2 136

__global__ void __launch_bounds__(512, 2)
p_kernel(const float* __restrict__ node_feat,
         const float* __restrict__ We1,
         int N, int pTiles)
{
    const int tid = threadIdx.x;

    if ((int)blockIdx.x >= pTiles) {
        const int zb = blockIdx.x - pTiles;
        float4* h4 = (float4*)g_hneigh;
        const int total4 = NN * HH / 4;
        for (int i = zb * 512 + tid; i < total4; i += (gridDim.x - pTiles) * 512)
            h4[i] = make_float4(0.f, 0.f, 0.f, 0.f);
        return;
    }

    extern __shared__ float sm[];
    float* As = sm;                 // 128*68
    float* Bs = As + 128 * ASTR;    // 64*136

    for (int i = tid; i < 64 * 128; i += 512) {
        int k = i >> 7, j = i & 127;
        float v = (j < 64) ? We1[k * HH + j] : We1[(64 + k) * HH + (j - 64)];
        Bs[k * BSTR2 + j] = __uint_as_float(f2tf(v));
    }
    const int base = blockIdx.x * 128;
    const float4* nf4 = (const float4*)node_feat;
    for (int idx = tid; idx < 128 * 16; idx += 512) {
        int r = idx >> 4, c = idx & 15;
        int n = base + r;
        if (n >= N) n = N - 1;
        ((float4*)(As + r * ASTR))[c] = nf4[(long)n * 16 + c];
    }
    __syncthreads();

    const int warp = tid >> 5, lane = tid & 31;
    const int gid = lane >> 2, tig = lane & 3;
    const int mrow  = (warp & 3) * 32;
    const int nbase = (warp >> 2) * 32;

    float d[2][4][4];
    #pragma unroll
    for (int mi = 0; mi < 2; mi++)
        #pragma unroll
        for (int nj = 0; nj < 4; nj++)
            #pragma unroll
            for (int q = 0; q < 4; q++) d[mi][nj][q] = 0.0f;

    const unsigned* bu = (const unsigned*)Bs;
    #pragma unroll
    for (int ks = 0; ks < 8; ks++) {
        const int kk = ks * 8;
        unsigned a[2][4];
        #pragma unroll
        for (int mi = 0; mi < 2; mi++) {
            int r0 = mrow + mi * 16 + gid;
            const float* fp  = As + r0 * ASTR + kk + tig;
            const float* fp8 = fp + 8 * ASTR;
            a[mi][0] = f2tf(fp[0]);
            a[mi][1] = f2tf(fp8[0]);
            a[mi][2] = f2tf(fp[4]);
            a[mi][3] = f2tf(fp8[4]);
        }
        #pragma unroll
        for (int nj = 0; nj < 4; nj++) {
            int n = nbase + nj * 8 + gid;
            unsigned bb[2];
            bb[0] = bu[(kk + tig) * BSTR2 + n];
            bb[1] = bu[(kk + tig + 4) * BSTR2 + n];
            mma_tf32(d[0][nj], a[0], bb);
            mma_tf32(d[1][nj], a[1], bb);
        }
    }
    #pragma unroll
    for (int mi = 0; mi < 2; mi++) {
        int r0 = mrow + mi * 16 + gid;
        #pragma unroll
        for (int nj = 0; nj < 4; nj++) {
            int c0 = nbase + nj * 8 + tig * 2;
            int n0 = base + r0, n1 = base + r0 + 8;
            if (n0 < N)
                *(float2*)(g_P + (long)n0 * 128 + c0)
                    = make_float2(d[mi][nj][0], d[mi][nj][1]);
            if (n1 < N)
                *(float2*)(g_P + (long)n1 * 128 + c0)
                    = make_float2(d[mi][nj][2], d[mi][nj][3]);
        }
    }
}

// ---------------------------------------------------------------------------
// Edge kernel. Single buf (presum -> m -> msg in-place), 3 CTAs/SM.
// Chunk-1 P gather issued BEFORE bulk drain (regs reuse dead accumulators).
// ---------------------------------------------------------------------------
#define ETHREADS 256

__global__ void __launch_bounds__(ETHREADS, 3)
edge_kernel(const float* __restrict__ coord,
            const float* __restrict__ edge_feat,
            const int*   __restrict__ src,
            const int*   __restrict__ dst,
            const float* __restrict__ We1,
            const float* __restrict__ be1,
            const float* __restrict__ We2,
            const float* __restrict__ be2,
            int E)
{
    extern __shared__ float sm[];
    float* W1s    = sm;                      // 24*72
    float* W2s    = W1s + K1S * WSTR;        // 64*72
    float* b1s    = W2s + HH * WSTR;         // 64
    float* b2s    = b1s + HH;                // 64
    int*   ds     = (int*)(b2s + HH);        // 128
    float* buf    = (float*)(ds + E_TILE);   // 128*68 (presum/m/msg)
    float* fsmall = buf + E_TILE * PSTR;     // 128*28
    // total 75520 B -> 3 CTAs/SM

    const int tid = threadIdx.x;

    for (int i = tid; i < K1S * HH; i += ETHREADS) {
        int r = i / HH, c = i % HH;
        float v = 0.0f;
        if (r < 16)       v = We1[(129 + r) * HH + c];
        else if (r == 16) v = We1[128 * HH + c];
        W1s[r * WSTR + c] = __uint_as_float(f2tf(v));
    }
    for (int i = tid; i < HH * HH; i += ETHREADS) {
        int r = i / HH, c = i % HH;
        W2s[r * WSTR + c] = __uint_as_float(f2tf(We2[i]));
    }
    if (tid < HH) { b1s[tid] = be1[tid]; b2s[tid] = be2[tid]; }
    for (int i = tid; i < E_TILE * 11; i += ETHREADS) {
        int r = i / 11, c = 17 + (i % 11);
        fsmall[r * FSSTR + c] = 0.0f;
    }

    const int warp = tid >> 5;
    const int lane = tid & 31;
    const int gid  = lane >> 2;
    const int tig  = lane & 3;
    const int mrow  = (warp & 3) * 32;
    const int nbase = (warp >> 2) * 32;
    const int half  = lane >> 4;            // 0/1
    const int j     = lane & 15;            // 0..15

    const float4* P4 = (const float4*)g_P;
    const unsigned fsb = (unsigned)__cvta_generic_to_shared(fsmall);
    const unsigned msb = (unsigned)__cvta_generic_to_shared(buf);

    __syncthreads();

    const int nTiles = (E + E_TILE - 1) / E_TILE;
    for (int t = blockIdx.x; t < nTiles; t += gridDim.x) {
        const int base = t * E_TILE;

        // ========== STAGE A: no writes to buf/ds ==========
        const int eb = base + warp * 16;
        int egi = eb + j; if (egi >= E) egi = E - 1;
        const int myidx = (lane < 16) ? src[egi] : dst[egi];

        #pragma unroll
        for (int r = 0; r < 2; r++) {
            int el = warp * 16 + r * 8 + (lane >> 2);
            int eg = base + el; if (eg >= E) eg = E - 1;
            int c = lane & 3;
            cp16(fsb + el * (FSSTR * 4) + c * 16,
                 edge_feat + (long)eg * 16 + c * 4);
        }
        asm volatile("cp.async.commit_group;");

        // radial (lanes 0..15) + dst idx kept in reg
        int s_r = __shfl_sync(0xffffffffu, myidx, j);
        int d_r = __shfl_sync(0xffffffffu, myidx, 16 + j);
        if (lane < 16) {
            float cx = coord[s_r * 3 + 0] - coord[d_r * 3 + 0];
            float cy = coord[s_r * 3 + 1] - coord[d_r * 3 + 1];
            float cz = coord[s_r * 3 + 2] - coord[d_r * 3 + 2];
            fsmall[(warp * 16 + j) * FSSTR + 16]
                = cx * cx + cy * cy + cz * cz;
        }

        // chunk-1 P gather: issue LDGs BEFORE the bulk drain so L2 latency
        // overlaps the scatter wait (registers here reuse dead accumulators)
        float4 ps1[4], pd1[4];
        #pragma unroll
        for (int i = 0; i < 4; i++) {
            int el = i * 2 + half;
            int s = __shfl_sync(0xffffffffu, myidx, el);
            int d = __shfl_sync(0xffffffffu, myidx, 16 + el);
            ps1[i] = P4[(long)s * 32 + j];
            pd1[i] = P4[(long)d * 32 + 16 + j];
        }

        // ========== drain previous tile's bulk scatter ==========
        asm volatile("cp.async.bulk.wait_group 0;" ::: "memory");
        __syncthreads();

        // chunk-1 store + chunk-2 load/store
        #pragma unroll
        for (int i = 0; i < 4; i++) {
            int el = warp * 16 + i * 2 + half;
            float4 v = make_float4(ps1[i].x + pd1[i].x, ps1[i].y + pd1[i].y,
                                   ps1[i].z + pd1[i].z, ps1[i].w + pd1[i].w);
            *(float4*)(buf + el * PSTR + j * 4) = v;
        }
        {
            float4 ps2[4], pd2[4];
            #pragma unroll
            for (int i = 0; i < 4; i++) {
                int el = (4 + i) * 2 + half;
                int s = __shfl_sync(0xffffffffu, myidx, el);
                int d = __shfl_sync(0xffffffffu, myidx, 16 + el);
                ps2[i] = P4[(long)s * 32 + j];
                pd2[i] = P4[(long)d * 32 + 16 + j];
            }
            #pragma unroll
            for (int i = 0; i < 4; i++) {
                int el = warp * 16 + (4 + i) * 2 + half;
                float4 v = make_float4(ps2[i].x + pd2[i].x, ps2[i].y + pd2[i].y,
                                       ps2[i].z + pd2[i].z, ps2[i].w + pd2[i].w);
                *(float4*)(buf + el * PSTR + j * 4) = v;
            }
        }
        if (lane >= 16) ds[warp * 16 + j] = d_r;

        asm volatile("cp.async.wait_group 0;");
        __syncthreads();

        // ========== GEMM1: [128,24]@[24,64] ==========
        float d1[2][4][4];
        #pragma unroll
        for (int mi = 0; mi < 2; mi++)
            #pragma unroll
            for (int nj = 0; nj < 4; nj++)
                #pragma unroll
                for (int q = 0; q < 4; q++) d1[mi][nj][q] = 0.0f;

        const unsigned* w1u = (const unsigned*)W1s;
        #pragma unroll
        for (int ks = 0; ks < 3; ks++) {
            const int kk = ks * 8;
            unsigned a[2][4];
            #pragma unroll
            for (int mi = 0; mi < 2; mi++) {
                int r0 = mrow + mi * 16 + gid;
                const float* fp  = fsmall + r0 * FSSTR + kk + tig;
                const float* fp8 = fp + 8 * FSSTR;
                a[mi][0] = f2tf(fp[0]);
                a[mi][1] = f2tf(fp8[0]);
                a[mi][2] = f2tf(fp[4]);
                a[mi][3] = f2tf(fp8[4]);
            }
            #pragma unroll
            for (int nj = 0; nj < 4; nj++) {
                int n = nbase + nj * 8 + gid;
                unsigned bb[2];
                bb[0] = w1u[(kk + tig) * WSTR + n];
                bb[1] = w1u[(kk + tig + 4) * WSTR + n];
                mma_tf32(d1[0][nj], a[0], bb);
                mma_tf32(d1[1][nj], a[1], bb);
            }
        }

        // ---- epilogue1 IN-PLACE ----
        #pragma unroll
        for (int mi = 0; mi < 2; mi++) {
            int r0 = mrow + mi * 16 + gid;
            #pragma unroll
            for (int nj = 0; nj < 4; nj++) {
                int c0 = nbase + nj * 8 + tig * 2;
                float bb0 = b1s[c0], bb1 = b1s[c0 + 1];
                float* p00 = buf + r0 * PSTR + c0;
                float* p10 = buf + (r0 + 8) * PSTR + c0;
                p00[0] = __uint_as_float(f2tf(silu(d1[mi][nj][0] + p00[0] + bb0)));
                p00[1] = __uint_as_float(f2tf(silu(d1[mi][nj][1] + p00[1] + bb1)));
                p10[0] = __uint_as_float(f2tf(silu(d1[mi][nj][2] + p10[0] + bb0)));
                p10[1] = __uint_as_float(f2tf(silu(d1[mi][nj][3] + p10[1] + bb1)));
            }
        }
        __syncthreads();

        // ========== GEMM2: [128,64]@[64,64] ==========
        float d2[2][4][4];
        #pragma unroll
        for (int mi = 0; mi < 2; mi++)
            #pragma unroll
            for (int nj = 0; nj < 4; nj++)
                #pragma unroll
                for (int q = 0; q < 4; q++) d2[mi][nj][q] = 0.0f;

        const unsigned* msu = (const unsigned*)buf;
        const unsigned* w2u = (const unsigned*)W2s;
        #pragma unroll
        for (int ks = 0; ks < 8; ks++) {
            const int kk = ks * 8;
            unsigned a[2][4];
            #pragma unroll
            for (int mi = 0; mi < 2; mi++) {
                int r0 = mrow + mi * 16 + gid;
                const unsigned* mp  = msu + r0 * PSTR + kk + tig;
                const unsigned* mp8 = mp + 8 * PSTR;
                a[mi][0] = mp[0];
                a[mi][1] = mp8[0];
                a[mi][2] = mp[4];
                a[mi][3] = mp8[4];
            }
            #pragma unroll
            for (int nj = 0; nj < 4; nj++) {
                int n = nbase + nj * 8 + gid;
                unsigned bb[2];
                bb[0] = w2u[(kk + tig) * WSTR + n];
                bb[1] = w2u[(kk + tig + 4) * WSTR + n];
                mma_tf32(d2[0][nj], a[0], bb);
                mma_tf32(d2[1][nj], a[1], bb);
            }
        }
        __syncthreads();

        // ---- epilogue2 IN-PLACE ----
        #pragma unroll
        for (int mi = 0; mi < 2; mi++) {
            int r0 = mrow + mi * 16 + gid;
            #pragma unroll
            for (int nj = 0; nj < 4; nj++) {
                int c0 = nbase + nj * 8 + tig * 2;
                float bb0 = b2s[c0], bb1 = b2s[c0 + 1];
                float* p00 = buf + r0 * PSTR + c0;
                float* p10 = buf + (r0 + 8) * PSTR + c0;
                p00[0] = silu(d2[mi][nj][0] + bb0);
                p00[1] = silu(d2[mi][nj][1] + bb1);
                p10[0] = silu(d2[mi][nj][2] + bb0);
                p10[1] = silu(d2[mi][nj][3] + bb1);
            }
        }
        __syncthreads();

        // ========== scatter: bulk add-reduce ==========
        asm volatile("fence.proxy.async.shared::cta;" ::: "memory");
        if (tid < E_TILE && base + tid < E) {
            bulk_red_add(g_hneigh + (long)ds[tid] * HH,
                         msb + tid * (PSTR * 4), HH * 4);
        }
        asm volatile("cp.async.bulk.commit_group;" ::: "memory");
    }
    asm volatile("cp.async.bulk.wait_group 0;" ::: "memory");
}

// ---------------------------------------------------------------------------
// Node kernel: tf32 mma, 1024 threads (32 warps, m16 x n32 warp tiles).
// z=[node_feat|h_neigh] (K=128), N_TILE=256.
// ---------------------------------------------------------------------------
#define N_TILE 256
#define ZSTR   132
#define MSTR   68
#define NTHREADS 1024

__global__ void __launch_bounds__(NTHREADS, 1)
node_kernel(const float* __restrict__ node_feat,
            const float* __restrict__ Wn1,
            const float* __restrict__ bn1,
            const float* __restrict__ Wn2,
            const float* __restrict__ bn2,
            float* __restrict__ out,
            int N)
{
    extern __shared__ float sm[];
    float* zs  = sm;                        // 256*132 (m aliases, stride 68)
    float* W1s = zs + N_TILE * ZSTR;        // 128*72
    float* W2s = W1s + 128 * WSTR;          // 64*72
    float* b1s = W2s + HH * WSTR;
    float* b2s = b1s + HH;

    const int tid = threadIdx.x;

    for (int i = tid; i < 128 * HH; i += NTHREADS) {
        int r = i / HH, c = i % HH;
        W1s[r * WSTR + c] = __uint_as_float(f2tf(Wn1[i]));
    }
    for (int i = tid; i < HH * DD; i += NTHREADS) {
        int r = i / DD, c = i % DD;
        W2s[r * WSTR + c] = __uint_as_float(f2tf(Wn2[i]));
    }
    if (tid < HH) { b1s[tid] = bn1[tid]; b2s[tid] = bn2[tid]; }

    const int warp = tid >> 5;
    const int lane = tid & 31;
    const int gid  = lane >> 2;
    const int tig  = lane & 3;
    const int mrow  = (warp & 15) * 16;     // 16 row-groups of 16
    const int nbase = (warp >> 4) * 32;     // 2 col-groups of 32

    const float4* nf4 = (const float4*)node_feat;
    const float4* hn4 = (const float4*)g_hneigh;

    const int nTiles = (N + N_TILE - 1) / N_TILE;
    for (int t = blockIdx.x; t < nTiles; t += gridDim.x) {
        const int base = t * N_TILE;
        __syncthreads();

        for (int idx = tid; idx < N_TILE * 32; idx += NTHREADS) {
            int nl = idx >> 5, c = idx & 31;
            int n = base + nl;
            if (n >= N) n = N - 1;
            float4 v = (c < 16) ? nf4[(long)n * 16 + c]
                                : hn4[(long)n * 16 + (c - 16)];
            ((float4*)(zs + nl * ZSTR))[c] = v;
        }
        __syncthreads();

        float d1[4][4];
        #pragma unroll
        for (int nj = 0; nj < 4; nj++)
            #pragma unroll
            for (int q = 0; q < 4; q++) d1[nj][q] = 0.0f;

        const unsigned* w1u = (const unsigned*)W1s;
        #pragma unroll 4
        for (int ks = 0; ks < 16; ks++) {
            const int kk = ks * 8;
            unsigned a[4];
            {
                int r0 = mrow + gid;
                const float* fp  = zs + r0 * ZSTR + kk + tig;
                const float* fp8 = fp + 8 * ZSTR;
                a[0] = f2tf(fp[0]);
                a[1] = f2tf(fp8[0]);
                a[2] = f2tf(fp[4]);
                a[3] = f2tf(fp8[4]);
            }
            #pragma unroll
            for (int nj = 0; nj < 4; nj++) {
                int n = nbase + nj * 8 + gid;
                unsigned bb[2];
                bb[0] = w1u[(kk + tig) * WSTR + n];
                bb[1] = w1u[(kk + tig + 4) * WSTR + n];
                mma_tf32(d1[nj], a, bb);
            }
        }
        __syncthreads();

        {
            int r0 = mrow + gid;
            #pragma unroll
            for (int nj = 0; nj < 4; nj++) {
                int c0 = nbase + nj * 8 + tig * 2;
                float bb0 = b1s[c0], bb1 = b1s[c0 + 1];
                zs[r0 * MSTR + c0]
                    = __uint_as_float(f2tf(silu(d1[nj][0] + bb0)));
                zs[r0 * MSTR + c0 + 1]
                    = __uint_as_float(f2tf(silu(d1[nj][1] + bb1)));
                zs[(r0 + 8) * MSTR + c0]
                    = __uint_as_float(f2tf(silu(d1[nj][2] + bb0)));
                zs[(r0 + 8) * MSTR + c0 + 1]
                    = __uint_as_float(f2tf(silu(d1[nj][3] + bb1)));
            }
        }
        __syncthreads();

        float d2[4][4];
        #pragma unroll
        for (int nj = 0; nj < 4; nj++)
            #pragma unroll
            for (int q = 0; q < 4; q++) d2[nj][q] = 0.0f;

        const unsigned* msu = (const unsigned*)zs;
        const unsigned* w2u = (const unsigned*)W2s;
        #pragma unroll
        for (int ks = 0; ks < 8; ks++) {
            const int kk = ks * 8;
            unsigned a[4];
            {
                int r0 = mrow + gid;
                const unsigned* mp  = msu + r0 * MSTR + kk + tig;
                const unsigned* mp8 = mp + 8 * MSTR;
                a[0] = mp[0];
                a[1] = mp8[0];
                a[2] = mp[4];
                a[3] = mp8[4];
            }
            #pragma unroll
            for (int nj = 0; nj < 4; nj++) {
                int n = nbase + nj * 8 + gid;
                unsigned bb[2];
                bb[0] = w2u[(kk + tig) * WSTR + n];
                bb[1] = w2u[(kk + tig + 4) * WSTR + n];
                mma_tf32(d2[nj], a, bb);
            }
        }

        {
            int r0 = mrow + gid;
            #pragma unroll
            for (int nj = 0; nj < 4; nj++) {
                int c0 = nbase + nj * 8 + tig * 2;
                float bb0 = b2s[c0], bb1 = b2s[c0 + 1];
                int n0 = base + r0, n1 = base + r0 + 8;
                if (n0 < N)
                    *(float2*)(out + (long)n0 * DD + c0)
                        = make_float2(d2[nj][0] + bb0, d2[nj][1] + bb1);
                if (n1 < N)
                    *(float2*)(out + (long)n1 * DD + c0)
                        = make_float2(d2[nj][2] + bb0, d2[nj][3] + bb1);
            }
        }
    }
}

// ---------------------------------------------------------------------------
extern "C" void kernel_launch(void* const* d_in, const int* in_sizes, int n_in,
                              void* d_out, int out_size)
{
    const float* node_feat = (const float*)d_in[0];
    const float* coord     = (const float*)d_in[1];
    const float* edge_feat = (const float*)d_in[2];
    const int*   src       = (const int*)d_in[3];
    const int*   dst       = (const int*)d_in[4];
    const float* We1       = (const float*)d_in[5];
    const float* be1       = (const float*)d_in[6];
    const float* We2       = (const float*)d_in[7];
    const float* be2       = (const float*)d_in[8];
    const float* Wn1       = (const float*)d_in[9];
    const float* bn1       = (const float*)d_in[10];
    const float* Wn2       = (const float*)d_in[11];
    const float* bn2       = (const float*)d_in[12];
    float* out = (float*)d_out;

    const int N = in_sizes[0] / DD;
    const int E = in_sizes[3];

    const size_t smem_p =
        (size_t)(128 * ASTR + 64 * BSTR2) * sizeof(float);
    const size_t smem_edge =
        (size_t)(K1S * WSTR + HH * WSTR + 2 * HH + E_TILE
                 + E_TILE * PSTR + E_TILE * FSSTR)
        * sizeof(float);   // 75520 B -> 3 CTAs/SM
    const size_t smem_node =
        (size_t)(N_TILE * ZSTR + 128 * WSTR + HH * WSTR + 2 * HH)
        * sizeof(float);

    cudaFuncSetAttribute(p_kernel,
                         cudaFuncAttributeMaxDynamicSharedMemorySize,
                         (int)smem_p);
    cudaFuncSetAttribute(edge_kernel,
                         cudaFuncAttributeMaxDynamicSharedMemorySize,
                         (int)smem_edge);
    cudaFuncSetAttribute(node_kernel,
                         cudaFuncAttributeMaxDynamicSharedMemorySize,
                         (int)smem_node);

    int numSMs = 148;
    cudaDeviceGetAttribute(&numSMs, cudaDevAttrMultiProcessorCount, 0);

    // 1) P precompute + zero g_hneigh (fused grid)
    int pTiles = (N + 127) / 128;
    p_kernel<<<pTiles + 120, 512, smem_p>>>(node_feat, We1, N, pTiles);

    // 2) edge MLP + bulk-reduce scatter (persistent, 3 CTAs/SM)
    int eTiles = (E + E_TILE - 1) / E_TILE;
    int eGrid = 3 * numSMs;
    if (eGrid > eTiles) eGrid = eTiles;
    edge_kernel<<<eGrid, ETHREADS, smem_edge>>>(
        coord, edge_feat, src, dst, We1, be1, We2, be2, E);

    // 3) node MLP
    int nTiles = (N + N_TILE - 1) / N_TILE;
    int nGrid = nTiles < numSMs ? nTiles : numSMs;
    node_kernel<<<nGrid, NTHREADS, smem_node>>>(
        node_feat, Wn1, bn1, Wn2, bn2, out, N);
}